// round 2
// baseline (speedup 1.0000x reference)
#include <cuda_runtime.h>

// ---------------------------------------------------------------------------
// Spikformer spatial+temporal SSA, fp32 SIMT implementation.
// Key exploits:
//  - LIF outputs are exactly binary -> spikes stored as {0,1} floats.
//  - attention (q k^T) v == q (k^T v) exactly (integer arithmetic in fp32).
//  - spike thresholds: conv: z*g+b >= 2 ; attention: integer count >= 8.
// ---------------------------------------------------------------------------

#define TT 10
#define BB 4
#define CC 384
#define NN 384
#define HH 12
#define CN (CC * NN)             // 147456
#define TBCN (TT * BB * CC * NN) // 5898240
#define BCN (BB * CC * NN)       // 589824

// scratch (static device globals; no allocation anywhere)
__device__ float g_q[TBCN];
__device__ float g_k[TBCN];
__device__ float g_v[TBCN];
__device__ float g_os[TBCN];   // attention-output spikes (t,b,c,n)
__device__ float g_a[TBCN];    // final conv spikes (reused: spatial a, then temporal bt)
__device__ float g_tq[TBCN];   // temporal-gathered layout [(n*B+b)*H+h][t*32+e]
__device__ float g_tk[TBCN];
__device__ float g_tv[TBCN];
__device__ float g_ared[TT * BB * CC];
__device__ float g_bred[BCN];

// ---------------------------------------------------------------------------
// Fused GEMM + BN + spike:  out[o,n] = ((sum_c W[o,c]*X[c,n])*g[o]+b[o] >= 2)
// 128x128 tile, BK=16, 256 threads, 8x8 microtile, double-buffered smem.
// 384 = 3*128, K=384 = 24*16 -> no bounds checks needed.
// ---------------------------------------------------------------------------
#define BM 128
#define BNb 128
#define BK 16
#define KT (CC / BK) // 24

__device__ __forceinline__ void gemm_spike_body(
    const float* __restrict__ W, const float* __restrict__ gs,
    const float* __restrict__ bs, const float* __restrict__ Xb,
    float* __restrict__ Ob)
{
    __shared__ float As[2][BK][BM];
    __shared__ float Bs[2][BK][BNb];

    const int tid = threadIdx.x;
    const int o0 = blockIdx.y * BM;
    const int n0 = blockIdx.x * BNb;

    // loader mapping
    const int a_oo = tid >> 2;          // 0..63
    const int a_k4 = (tid & 3) << 2;    // 0,4,8,12
    const int b_kk = tid >> 5;          // 0..7
    const int b_nf = (tid & 31) << 2;   // 0..124

    const float* Ap = W + (o0 + a_oo) * CC + a_k4;
    const float* Bp = Xb + b_kk * NN + n0 + b_nf;

    float4 ar0 = *(const float4*)(Ap);
    float4 ar1 = *(const float4*)(Ap + 64 * CC);
    float4 br0 = *(const float4*)(Bp);
    float4 br1 = *(const float4*)(Bp + 8 * NN);

    As[0][a_k4 + 0][a_oo] = ar0.x;
    As[0][a_k4 + 1][a_oo] = ar0.y;
    As[0][a_k4 + 2][a_oo] = ar0.z;
    As[0][a_k4 + 3][a_oo] = ar0.w;
    As[0][a_k4 + 0][a_oo + 64] = ar1.x;
    As[0][a_k4 + 1][a_oo + 64] = ar1.y;
    As[0][a_k4 + 2][a_oo + 64] = ar1.z;
    As[0][a_k4 + 3][a_oo + 64] = ar1.w;
    *(float4*)&Bs[0][b_kk][b_nf] = br0;
    *(float4*)&Bs[0][b_kk + 8][b_nf] = br1;
    __syncthreads();

    float acc[8][8];
#pragma unroll
    for (int i = 0; i < 8; ++i)
#pragma unroll
        for (int j = 0; j < 8; ++j) acc[i][j] = 0.0f;

    const int ao = (tid >> 4) << 3; // 0..120
    const int bn = (tid & 15) << 3; // 0..120

    for (int kt = 0; kt < KT; ++kt) {
        const int cur = kt & 1;
        if (kt + 1 < KT) {
            const float* Ap2 = Ap + (kt + 1) * BK;
            const float* Bp2 = Bp + (kt + 1) * BK * NN;
            ar0 = *(const float4*)(Ap2);
            ar1 = *(const float4*)(Ap2 + 64 * CC);
            br0 = *(const float4*)(Bp2);
            br1 = *(const float4*)(Bp2 + 8 * NN);
        }
#pragma unroll
        for (int kk = 0; kk < BK; ++kk) {
            float a[8], b[8];
            *(float4*)(a)     = *(const float4*)&As[cur][kk][ao];
            *(float4*)(a + 4) = *(const float4*)&As[cur][kk][ao + 4];
            *(float4*)(b)     = *(const float4*)&Bs[cur][kk][bn];
            *(float4*)(b + 4) = *(const float4*)&Bs[cur][kk][bn + 4];
#pragma unroll
            for (int i = 0; i < 8; ++i)
#pragma unroll
                for (int j = 0; j < 8; ++j)
                    acc[i][j] = fmaf(a[i], b[j], acc[i][j]);
        }
        if (kt + 1 < KT) {
            const int nxt = cur ^ 1;
            As[nxt][a_k4 + 0][a_oo] = ar0.x;
            As[nxt][a_k4 + 1][a_oo] = ar0.y;
            As[nxt][a_k4 + 2][a_oo] = ar0.z;
            As[nxt][a_k4 + 3][a_oo] = ar0.w;
            As[nxt][a_k4 + 0][a_oo + 64] = ar1.x;
            As[nxt][a_k4 + 1][a_oo + 64] = ar1.y;
            As[nxt][a_k4 + 2][a_oo + 64] = ar1.z;
            As[nxt][a_k4 + 3][a_oo + 64] = ar1.w;
            *(float4*)&Bs[nxt][b_kk][b_nf] = br0;
            *(float4*)&Bs[nxt][b_kk + 8][b_nf] = br1;
        }
        __syncthreads();
    }

#pragma unroll
    for (int i = 0; i < 8; ++i) {
        const int o = o0 + ao + i;
        const float gv = gs[o];
        const float bv = bs[o];
        float4 r0, r1;
        r0.x = (fmaf(acc[i][0], gv, bv) >= 2.0f) ? 1.0f : 0.0f;
        r0.y = (fmaf(acc[i][1], gv, bv) >= 2.0f) ? 1.0f : 0.0f;
        r0.z = (fmaf(acc[i][2], gv, bv) >= 2.0f) ? 1.0f : 0.0f;
        r0.w = (fmaf(acc[i][3], gv, bv) >= 2.0f) ? 1.0f : 0.0f;
        r1.x = (fmaf(acc[i][4], gv, bv) >= 2.0f) ? 1.0f : 0.0f;
        r1.y = (fmaf(acc[i][5], gv, bv) >= 2.0f) ? 1.0f : 0.0f;
        r1.z = (fmaf(acc[i][6], gv, bv) >= 2.0f) ? 1.0f : 0.0f;
        r1.w = (fmaf(acc[i][7], gv, bv) >= 2.0f) ? 1.0f : 0.0f;
        float* dst = Ob + (size_t)o * NN + n0 + bn;
        *(float4*)(dst) = r0;
        *(float4*)(dst + 4) = r1;
    }
}

// qkv projections fused in one launch: grid (3,3,120), z = j*40 + tb
__global__ void __launch_bounds__(256) k_qkv_gemm(
    const float* __restrict__ W4, const float* __restrict__ g4,
    const float* __restrict__ b4, const float* __restrict__ x,
    const float* __restrict__ y)
{
    const int z = blockIdx.z;
    const int j = z / (TT * BB);
    const int tb = z - j * (TT * BB);
    const float* W = W4 + j * CC * CC;
    const float* gs = g4 + j * CC;
    const float* bs = b4 + j * CC;
    const float* Xb = ((j == 0) ? x : y) + (size_t)tb * CN;
    float* Ob = ((j == 0) ? g_q : (j == 1) ? g_k : g_v) + (size_t)tb * CN;
    gemm_spike_body(W, gs, bs, Xb, Ob);
}

// final conv (W[3]) on attention-output spikes: grid (3,3,40)
__global__ void __launch_bounds__(256) k_final_gemm(
    const float* __restrict__ W, const float* __restrict__ gs,
    const float* __restrict__ bs)
{
    const int tb = blockIdx.z;
    gemm_spike_body(W, gs, bs, g_os + (size_t)tb * CN, g_a + (size_t)tb * CN);
}

// ---------------------------------------------------------------------------
// Spatial attention, per (t,b,h):  M = k^T v (32x32 integer), o = q M, spike o>=8
// grid = T*B*H = 480, 256 threads.
// ---------------------------------------------------------------------------
__global__ void __launch_bounds__(256) k_spatial_attn()
{
    __shared__ float ks[64][33];
    __shared__ float vs[64][33];
    __shared__ float Ms[32][33];

    const int blk = blockIdx.x;
    const int tb = blk / HH;
    const int h = blk - tb * HH;
    const size_t base = (size_t)tb * CN + (size_t)h * 32 * NN;
    const float* qb = g_q + base;
    const float* kb = g_k + base;
    const float* vb = g_v + base;
    float* ob = g_os + base;
    const int tid = threadIdx.x;

    // Phase 1: M[e][dd] = sum_m k[m,e]*v[m,dd]
    const int e = tid >> 3;            // 0..31
    const int dd0 = (tid & 7) << 2;    // 0..28
    float mc0 = 0.f, mc1 = 0.f, mc2 = 0.f, mc3 = 0.f;
    for (int m0 = 0; m0 < NN; m0 += 64) {
#pragma unroll
        for (int i = 0; i < 8; ++i) {
            int idx = tid + i * 256;
            int ee = idx >> 6, mm = idx & 63;
            ks[mm][ee] = kb[(size_t)ee * NN + m0 + mm];
            vs[mm][ee] = vb[(size_t)ee * NN + m0 + mm];
        }
        __syncthreads();
#pragma unroll 8
        for (int mm = 0; mm < 64; ++mm) {
            float kv = ks[mm][e];
            mc0 = fmaf(kv, vs[mm][dd0 + 0], mc0);
            mc1 = fmaf(kv, vs[mm][dd0 + 1], mc1);
            mc2 = fmaf(kv, vs[mm][dd0 + 2], mc2);
            mc3 = fmaf(kv, vs[mm][dd0 + 3], mc3);
        }
        __syncthreads();
    }
    Ms[e][dd0 + 0] = mc0;
    Ms[e][dd0 + 1] = mc1;
    Ms[e][dd0 + 2] = mc2;
    Ms[e][dd0 + 3] = mc3;
    __syncthreads();

    // Phase 2: o[n,dd] = sum_e q[n,e]*M[e,dd], spike >= 8 (exact integers)
    const int n_lane = tid & 63;
    const int d0 = (tid >> 6) << 3; // 0,8,16,24
    for (int n0 = 0; n0 < NN; n0 += 64) {
#pragma unroll
        for (int i = 0; i < 8; ++i) {
            int idx = tid + i * 256;
            int ee = idx >> 6, nn = idx & 63;
            ks[nn][ee] = qb[(size_t)ee * NN + n0 + nn]; // reuse ks as q-tile
        }
        __syncthreads();
        float oa[8];
#pragma unroll
        for (int j = 0; j < 8; ++j) oa[j] = 0.f;
#pragma unroll
        for (int ee = 0; ee < 32; ++ee) {
            float qv = ks[n_lane][ee];
#pragma unroll
            for (int j = 0; j < 8; ++j) oa[j] = fmaf(qv, Ms[ee][d0 + j], oa[j]);
        }
#pragma unroll
        for (int j = 0; j < 8; ++j)
            ob[(size_t)(d0 + j) * NN + n0 + n_lane] = (oa[j] >= 8.0f) ? 1.0f : 0.0f;
        __syncthreads();
    }
}

// ---------------------------------------------------------------------------
// Gather spikes into temporal layout: dst[((n*B+b)*H+h)*320 + t*32 + e]
// grid = 3 * 480 * 12 = 17280 (tensor, tbh, ntile), 256 threads, 32x32 transpose
// ---------------------------------------------------------------------------
__global__ void __launch_bounds__(256) k_gather_temporal()
{
    const int bx = blockIdx.x;
    const int which = bx / 5760;
    const int r = bx - which * 5760;
    const int ntile = r % 12;
    const int tbh = r / 12;
    const int tb = tbh / 12;
    const int h = tbh - tb * 12;
    const int t = tb / BB;
    const int b = tb - t * BB;

    const float* srcbase = (which == 0) ? g_q : (which == 1) ? g_k : g_v;
    float* dst = (which == 0) ? g_tq : (which == 1) ? g_tk : g_tv;
    const float* src = srcbase + (size_t)tb * CN + (size_t)h * 32 * NN + ntile * 32;

    __shared__ float tile[32][33];
    const int tid = threadIdx.x;
#pragma unroll
    for (int i = 0; i < 4; ++i) {
        int idx = tid + i * 256;
        int ee = idx >> 5, nn = idx & 31;
        tile[ee][nn] = src[(size_t)ee * NN + nn];
    }
    __syncthreads();
#pragma unroll
    for (int i = 0; i < 4; ++i) {
        int idx = tid + i * 256;
        int nn = idx >> 5, ee = idx & 31;
        int n = ntile * 32 + nn;
        dst[((size_t)(n * BB + b) * HH + h) * 320 + t * 32 + ee] = tile[ee][nn];
    }
}

// ---------------------------------------------------------------------------
// Temporal attention per (n,b,h): attn (10x10), o = attn v, spike >= 8,
// scatter through the torch reshape shuffle flat = h*320+t*32+dd -> (t',c').
// 8 groups (warps) per block; grid = 18432/8 = 2304.
// ---------------------------------------------------------------------------
__global__ void __launch_bounds__(256) k_temporal_attn()
{
    __shared__ float qs[8][321];   // transposed [e*10+t]
    __shared__ float ks2[8][321];  // transposed [e*10+s]
    __shared__ float vs2[8][321];  // natural    [s*32+dd]
    __shared__ float at[8][112];   // attn[t*10+s]

    const int wid = threadIdx.x >> 5;
    const int lane = threadIdx.x & 31;
    const int nbh = blockIdx.x * 8 + wid; // (n*B+b)*H+h
    const int h = nbh % HH;
    const int nb = nbh / HH;
    const int b = nb % BB;
    const int n = nb / BB;

    const float* qg = g_tq + (size_t)nbh * 320;
    const float* kg = g_tk + (size_t)nbh * 320;
    const float* vg = g_tv + (size_t)nbh * 320;

#pragma unroll
    for (int i = 0; i < TT; ++i) {
        qs[wid][lane * TT + i] = qg[i * 32 + lane];
        ks2[wid][lane * TT + i] = kg[i * 32 + lane];
        vs2[wid][i * 32 + lane] = vg[i * 32 + lane];
    }
    __syncwarp();

    for (int ii = lane; ii < 100; ii += 32) {
        int t = ii / 10, s = ii - t * 10;
        float acc = 0.f;
#pragma unroll
        for (int ee = 0; ee < 32; ++ee)
            acc = fmaf(qs[wid][ee * TT + t], ks2[wid][ee * TT + s], acc);
        at[wid][ii] = acc;
    }
    __syncwarp();

#pragma unroll
    for (int t = 0; t < TT; ++t) {
        float acc = 0.f;
#pragma unroll
        for (int s = 0; s < TT; ++s)
            acc = fmaf(at[wid][t * 10 + s], vs2[wid][s * 32 + lane], acc);
        float sp = (acc >= 8.0f) ? 1.0f : 0.0f;
        int flat = h * 320 + t * 32 + lane;
        int tp = flat / 384;
        int cp = flat - tp * 384;
        g_os[((size_t)(tp * BB + b) * CC + cp) * NN + n] = sp;
    }
}

// ---------------------------------------------------------------------------
// reductions + outer product
// ---------------------------------------------------------------------------
__global__ void __launch_bounds__(256) k_reduce_a() // 1920 blocks: 8 rows/block
{
    const int row = blockIdx.x * 8 + (threadIdx.x >> 5);
    const int lane = threadIdx.x & 31;
    const float* p = g_a + (size_t)row * NN;
    float s = 0.f;
#pragma unroll
    for (int i = lane; i < NN; i += 32) s += p[i];
#pragma unroll
    for (int o = 16; o; o >>= 1) s += __shfl_xor_sync(0xffffffffu, s, o);
    if (lane == 0) g_ared[row] = s / (float)NN;
}

__global__ void __launch_bounds__(256) k_reduce_b() // 2304 blocks
{
    const int i = blockIdx.x * 256 + threadIdx.x;
    float s = 0.f;
#pragma unroll
    for (int t = 0; t < TT; ++t) s += g_a[(size_t)t * BCN + i];
    g_bred[i] = s / (float)TT;
}

__global__ void __launch_bounds__(256) k_outer(float* __restrict__ out) // 23040 blocks
{
    const int i = blockIdx.x * 256 + threadIdx.x;
    const int n = i % NN;
    const int rest = i / NN;
    const int c = rest % CC;
    const int tb = rest / CC;
    const int b = tb % BB;
    out[i] = g_ared[tb * CC + c] * g_bred[((size_t)b * CC + c) * NN + n];
}

// ---------------------------------------------------------------------------
extern "C" void kernel_launch(void* const* d_in, const int* in_sizes, int n_in,
                              void* d_out, int out_size)
{
    const float* x  = (const float*)d_in[0];
    const float* y  = (const float*)d_in[1];
    const float* sW = (const float*)d_in[2];
    const float* sg = (const float*)d_in[3];
    const float* sb = (const float*)d_in[4];
    const float* tW = (const float*)d_in[5];
    const float* tg = (const float*)d_in[6];
    const float* tbn = (const float*)d_in[7];
    float* out = (float*)d_out;

    dim3 gq(3, 3, 3 * TT * BB); // 120 batch-proj blocks in z
    dim3 gf(3, 3, TT * BB);     // 40

    // ---- spatial path ----
    k_qkv_gemm<<<gq, 256>>>(sW, sg, sb, x, y);
    k_spatial_attn<<<TT * BB * HH, 256>>>();
    k_final_gemm<<<gf, 256>>>(sW + 3 * CC * CC, sg + 3 * CC, sb + 3 * CC);
    k_reduce_a<<<(TT * BB * CC) / 8, 256>>>();

    // ---- temporal path ----
    k_qkv_gemm<<<gq, 256>>>(tW, tg, tbn, x, y);
    k_gather_temporal<<<3 * 480 * 12, 256>>>();
    k_temporal_attn<<<(NN * BB * HH) / 8, 256>>>();
    k_final_gemm<<<gf, 256>>>(tW + 3 * CC * CC, tg + 3 * CC, tbn + 3 * CC);
    k_reduce_b<<<BCN / 256, 256>>>();

    // ---- combine ----
    k_outer<<<TBCN / 256, 256>>>(out);
}

// round 4
// speedup vs baseline: 1.0585x; 1.0585x over previous
#include <cuda_runtime.h>
#include <cuda_bf16.h>
#include <cstdint>

// ---------------------------------------------------------------------------
// Spikformer spatial+temporal SSA — bf16 mma.sync tensor-core implementation.
//  - LIF outputs exactly binary; thresholds exact (>=2 conv, >=8 attention).
//  - fp32 = 3x bf16 split (exact); GEMM = 6 bf16 MMA term-pairs (fp32-exact),
//    final conv (binary B) = 3 term-pairs.
//  - tcgen05 unavailable (harness PTX target is sm_103, not sm_103a) ->
//    warp-level mma.sync.m16n8k16 bf16 (plain sm_80+ PTX).
// ---------------------------------------------------------------------------

#define TT 10
#define BB 4
#define CC 384
#define NN 384
#define HH 12
#define CN (CC * NN)             // 147456
#define TBCN (TT * BB * CC * NN) // 5898240
#define BCN (BB * CC * NN)       // 589824

// scratch
__device__ __align__(128) float g_q[TBCN];
__device__ __align__(128) float g_k[TBCN];
__device__ __align__(128) float g_v[TBCN];
__device__ __align__(128) float g_a[TBCN];
__device__ __align__(128) float g_tq[TBCN];
__device__ __align__(128) float g_tk[TBCN];
__device__ __align__(128) float g_tv[TBCN];
__device__ __align__(128) __nv_bfloat16 g_osT[TBCN];           // [tb][n][c] spikes
__device__ __align__(128) __nv_bfloat16 g_Wc[8 * 3 * CN];      // [mat 0..7][comp][o][c]
__device__ __align__(128) __nv_bfloat16 g_XT[2 * 3 * 40 * CN]; // [sel][comp][tb][n][c]
__device__ float g_ared[TT * BB * CC];
__device__ float g_bred[BCN];

__device__ __forceinline__ uint32_t smem_u32(const void* p) {
    uint32_t a;
    asm("{ .reg .u64 t; cvta.to.shared.u64 t, %1; cvt.u32.u64 %0, t; }"
        : "=r"(a) : "l"(p));
    return a;
}

__device__ __forceinline__ void ldsm_x4(uint32_t addr, uint32_t& r0, uint32_t& r1,
                                        uint32_t& r2, uint32_t& r3) {
    asm volatile("ldmatrix.sync.aligned.m8n8.x4.shared.b16 {%0,%1,%2,%3}, [%4];"
                 : "=r"(r0), "=r"(r1), "=r"(r2), "=r"(r3) : "r"(addr));
}

__device__ __forceinline__ void mma_bf16(float* c, uint32_t a0, uint32_t a1,
                                         uint32_t a2, uint32_t a3,
                                         uint32_t b0, uint32_t b1) {
    asm volatile(
        "mma.sync.aligned.m16n8k16.row.col.f32.bf16.bf16.f32 "
        "{%0,%1,%2,%3}, {%4,%5,%6,%7}, {%8,%9}, {%0,%1,%2,%3};"
        : "+f"(c[0]), "+f"(c[1]), "+f"(c[2]), "+f"(c[3])
        : "r"(a0), "r"(a1), "r"(a2), "r"(a3), "r"(b0), "r"(b1));
}

__device__ __forceinline__ uint32_t swz(uint32_t off) {
    return off ^ ((off >> 3) & 0x70);
}

#define SMEM_QKV 99328
#define SMEM_FIN 66560

// ---------------------------------------------------------------------------
// fp32 -> 3x bf16 exact split precompute
// ---------------------------------------------------------------------------
__device__ __forceinline__ void split3(float x, __nv_bfloat16& a, __nv_bfloat16& b,
                                       __nv_bfloat16& c) {
    a = __float2bfloat16(x);
    float r = x - __bfloat162float(a);
    b = __float2bfloat16(r);
    float r2 = r - __bfloat162float(b);
    c = __float2bfloat16(r2);
}

__global__ void __launch_bounds__(256) k_split_w(const float* __restrict__ sW,
                                                 const float* __restrict__ tW) {
    int i = blockIdx.x * 256 + threadIdx.x; // < 1179648
    float w = (i < 4 * CN) ? sW[i] : tW[i - 4 * CN];
    int m = i / CN, e = i - m * CN;
    __nv_bfloat16 c1, c2, c3;
    split3(w, c1, c2, c3);
    size_t base = (size_t)m * 3 * CN + e;
    g_Wc[base] = c1;
    g_Wc[base + CN] = c2;
    g_Wc[base + 2 * CN] = c3;
}

// transpose + split x/y: out [sel][comp][tb][n][c]
__global__ void __launch_bounds__(256) k_split_xy(const float* __restrict__ x,
                                                  const float* __restrict__ y) {
    __shared__ float t[32][33];
    int bx = blockIdx.x;
    int sel = bx / 5760;
    int r = bx - sel * 5760;
    int tb = r / 144, tl = r - tb * 144;
    int ct = tl / 12, nt = tl - ct * 12;
    const float* src = (sel ? y : x) + (size_t)tb * CN + (size_t)(ct * 32) * NN + nt * 32;
    int tid = threadIdx.x;
#pragma unroll
    for (int i = 0; i < 4; ++i) {
        int idx = tid + i * 256;
        int cl = idx >> 5, nl = idx & 31;
        t[cl][nl] = src[(size_t)cl * NN + nl];
    }
    __syncthreads();
#pragma unroll
    for (int i = 0; i < 4; ++i) {
        int idx = tid + i * 256;
        int nl = idx >> 5, cl = idx & 31;
        __nv_bfloat16 c1, c2, c3;
        split3(t[cl][nl], c1, c2, c3);
        size_t base = ((size_t)(sel * 3) * 40 + tb) * CN + (size_t)(nt * 32 + nl) * CC + ct * 32 + cl;
        g_XT[base] = c1;
        g_XT[base + (size_t)40 * CN] = c2;
        g_XT[base + (size_t)80 * CN] = c3;
    }
}

// ---------------------------------------------------------------------------
// Tensor-core GEMM tile: D[128,128] = sum_pairs A_pa[128,384] * B_pb[128,384]^T
// (both operands K-major). mma.sync m16n8k16 bf16, warp tile 64x32.
// ---------------------------------------------------------------------------
template <int NBC>
__device__ __forceinline__ void tc_gemm_body(
    const __nv_bfloat16* __restrict__ A0,
    const __nv_bfloat16* __restrict__ B0, size_t bcs,
    const float* __restrict__ gs, const float* __restrict__ bs,
    float* __restrict__ Ob, int o0, int n0)
{
    extern __shared__ char smem_raw[];
    const uint32_t ab = (smem_u32(smem_raw) + 1023u) & ~1023u;
    const uint32_t Aoff = ab;
    const uint32_t Boff = ab + 49152;
    const int tid = threadIdx.x;
    const int wid = tid >> 5;
    const int lane = tid & 31;
    const int wm = (wid >> 2) * 64;  // warp m origin (0 or 64)
    const int wn = (wid & 3) * 32;   // warp n origin

    float acc[4][4][4];
#pragma unroll
    for (int mi = 0; mi < 4; ++mi)
#pragma unroll
        for (int ni = 0; ni < 4; ++ni)
#pragma unroll
            for (int r = 0; r < 4; ++r) acc[mi][ni][r] = 0.0f;

    // ldmatrix per-thread row/col offsets
    const int a_row_l = lane & 15;
    const int a_ch = (lane >> 4) << 4;                  // 0 / 16 bytes
    const int b_row_l = ((lane >> 4) & 1) * 8 + (lane & 7);
    const int b_ch = ((lane >> 3) & 1) << 4;

    // loader mapping (same as data layout: 128 rows x 64 bf16, SW128 swizzle)
    for (int kb = 0; kb < 6; ++kb) {
        const int k0 = kb * 64;
#pragma unroll
        for (int i = 0; i < 12; ++i) {
            int idx = tid + i * 256;
            int comp = idx >> 10;
            int rem = idx & 1023;
            int row = rem >> 3, ch = rem & 7;
            uint4 v = *(const uint4*)(A0 + (size_t)comp * CN + row * CC + k0 + ch * 8);
            uint32_t sa = Aoff + comp * 16384 + swz((uint32_t)(row * 128 + ch * 16));
            asm volatile("st.shared.v4.b32 [%0], {%1,%2,%3,%4};"
                         :: "r"(sa), "r"(v.x), "r"(v.y), "r"(v.z), "r"(v.w) : "memory");
        }
#pragma unroll
        for (int i = 0; i < NBC * 4; ++i) {
            int idx = tid + i * 256;
            int comp = idx >> 10;
            int rem = idx & 1023;
            int row = rem >> 3, ch = rem & 7;
            uint4 v = *(const uint4*)(B0 + (size_t)comp * bcs + row * CC + k0 + ch * 8);
            uint32_t sa = Boff + comp * 16384 + swz((uint32_t)(row * 128 + ch * 16));
            asm volatile("st.shared.v4.b32 [%0], {%1,%2,%3,%4};"
                         :: "r"(sa), "r"(v.x), "r"(v.y), "r"(v.z), "r"(v.w) : "memory");
        }
        __syncthreads();

        const int npairs = (NBC == 3) ? 6 : 3;
#pragma unroll
        for (int p = 0; p < 6; ++p) {
            if (p >= npairs) break;
            int pa, pb;
            if (NBC == 3) {
                const int PA[6] = {0, 0, 1, 0, 1, 2};
                const int PB[6] = {0, 1, 0, 2, 1, 0};
                pa = PA[p]; pb = PB[p];
            } else {
                pa = p; pb = 0;
            }
            const uint32_t abase = Aoff + pa * 16384;
            const uint32_t bbase = Boff + pb * 16384;
#pragma unroll
            for (int ks = 0; ks < 4; ++ks) {
                uint32_t afr[4][4];
#pragma unroll
                for (int mi = 0; mi < 4; ++mi) {
                    int row = wm + mi * 16 + a_row_l;
                    uint32_t off = (uint32_t)(row * 128 + ks * 32 + a_ch);
                    ldsm_x4(abase + swz(off), afr[mi][0], afr[mi][1], afr[mi][2], afr[mi][3]);
                }
                uint32_t bfr[4][2];
#pragma unroll
                for (int bi = 0; bi < 2; ++bi) {
                    int row = wn + bi * 16 + b_row_l;
                    uint32_t off = (uint32_t)(row * 128 + ks * 32 + b_ch);
                    uint32_t r0, r1, r2, r3;
                    ldsm_x4(bbase + swz(off), r0, r1, r2, r3);
                    bfr[bi * 2][0] = r0; bfr[bi * 2][1] = r1;
                    bfr[bi * 2 + 1][0] = r2; bfr[bi * 2 + 1][1] = r3;
                }
#pragma unroll
                for (int mi = 0; mi < 4; ++mi)
#pragma unroll
                    for (int ni = 0; ni < 4; ++ni)
                        mma_bf16(acc[mi][ni], afr[mi][0], afr[mi][1], afr[mi][2],
                                 afr[mi][3], bfr[ni][0], bfr[ni][1]);
            }
        }
        __syncthreads();
    }

    // epilogue: BN + spike, store fp32
#pragma unroll
    for (int mi = 0; mi < 4; ++mi) {
        const int r0 = o0 + wm + mi * 16 + (lane >> 2);
#pragma unroll
        for (int half = 0; half < 2; ++half) {
            const int row = r0 + half * 8;
            const float gv = gs[row];
            const float bv = bs[row];
            float* dst = Ob + (size_t)row * NN + n0 + wn + (lane & 3) * 2;
#pragma unroll
            for (int ni = 0; ni < 4; ++ni) {
                float2 w;
                w.x = (fmaf(acc[mi][ni][half * 2 + 0], gv, bv) >= 2.0f) ? 1.f : 0.f;
                w.y = (fmaf(acc[mi][ni][half * 2 + 1], gv, bv) >= 2.0f) ? 1.f : 0.f;
                *(float2*)(dst + ni * 8) = w;
            }
        }
    }
}

// qkv: grid (3 ntile, 3 mtile, 120 = j*40+tb)
__global__ void __launch_bounds__(256, 2) k_qkv_tc(const float* __restrict__ g4,
                                                   const float* __restrict__ b4, int path) {
    int z = blockIdx.z;
    int j = z / 40, tb = z - j * 40;
    int o0 = blockIdx.y * 128, n0 = blockIdx.x * 128;
    const __nv_bfloat16* A0 = g_Wc + (size_t)((path * 4 + j) * 3) * CN + (size_t)o0 * CC;
    int sel = (j == 0) ? 0 : 1;
    const __nv_bfloat16* B0 = g_XT + ((size_t)(sel * 3) * 40 + tb) * CN + (size_t)n0 * CC;
    float* Ob = ((j == 0) ? g_q : (j == 1) ? g_k : g_v) + (size_t)tb * CN;
    tc_gemm_body<3>(A0, B0, (size_t)40 * CN, g4 + j * CC, b4 + j * CC, Ob, o0, n0);
}

// final conv: grid (3,3,40); B = osT spikes (single bf16 comp)
__global__ void __launch_bounds__(256, 2) k_final_tc(const float* __restrict__ g4,
                                                     const float* __restrict__ b4, int path) {
    int tb = blockIdx.z;
    int o0 = blockIdx.y * 128, n0 = blockIdx.x * 128;
    const __nv_bfloat16* A0 = g_Wc + (size_t)((path * 4 + 3) * 3) * CN + (size_t)o0 * CC;
    const __nv_bfloat16* B0 = g_osT + (size_t)tb * CN + (size_t)n0 * CC;
    tc_gemm_body<1>(A0, B0, 0, g4 + 3 * CC, b4 + 3 * CC, g_a + (size_t)tb * CN, o0, n0);
}

// ---------------------------------------------------------------------------
// Spatial attention per (t,b,h): M = k^T v (32x32), o = q M, spike >= 8.
// Writes transposed bf16 spikes into g_osT[tb][n][c].
// ---------------------------------------------------------------------------
__global__ void __launch_bounds__(256) k_spatial_attn() {
    __shared__ float ks[64][33];
    __shared__ float vs[64][33];
    __shared__ float Ms[32][33];

    const int blk = blockIdx.x;
    const int tb = blk / HH;
    const int h = blk - tb * HH;
    const size_t base = (size_t)tb * CN + (size_t)h * 32 * NN;
    const float* qb = g_q + base;
    const float* kb = g_k + base;
    const float* vb = g_v + base;
    const int tid = threadIdx.x;

    const int e = tid >> 3;
    const int dd0 = (tid & 7) << 2;
    float mc0 = 0.f, mc1 = 0.f, mc2 = 0.f, mc3 = 0.f;
    for (int m0 = 0; m0 < NN; m0 += 64) {
#pragma unroll
        for (int i = 0; i < 8; ++i) {
            int idx = tid + i * 256;
            int ee = idx >> 6, mm = idx & 63;
            ks[mm][ee] = kb[(size_t)ee * NN + m0 + mm];
            vs[mm][ee] = vb[(size_t)ee * NN + m0 + mm];
        }
        __syncthreads();
#pragma unroll 8
        for (int mm = 0; mm < 64; ++mm) {
            float kv = ks[mm][e];
            mc0 = fmaf(kv, vs[mm][dd0 + 0], mc0);
            mc1 = fmaf(kv, vs[mm][dd0 + 1], mc1);
            mc2 = fmaf(kv, vs[mm][dd0 + 2], mc2);
            mc3 = fmaf(kv, vs[mm][dd0 + 3], mc3);
        }
        __syncthreads();
    }
    Ms[e][dd0 + 0] = mc0;
    Ms[e][dd0 + 1] = mc1;
    Ms[e][dd0 + 2] = mc2;
    Ms[e][dd0 + 3] = mc3;
    __syncthreads();

    const int n_lane = tid & 63;
    const int d0 = (tid >> 6) << 3;
    for (int n0 = 0; n0 < NN; n0 += 64) {
#pragma unroll
        for (int i = 0; i < 8; ++i) {
            int idx = tid + i * 256;
            int ee = idx >> 6, nn = idx & 63;
            ks[nn][ee] = qb[(size_t)ee * NN + n0 + nn];
        }
        __syncthreads();
        float oa[8];
#pragma unroll
        for (int j = 0; j < 8; ++j) oa[j] = 0.f;
#pragma unroll
        for (int ee = 0; ee < 32; ++ee) {
            float qv = ks[n_lane][ee];
#pragma unroll
            for (int j = 0; j < 8; ++j) oa[j] = fmaf(qv, Ms[ee][d0 + j], oa[j]);
        }
        const int n = n0 + n_lane;
        __nv_bfloat16* op = g_osT + (size_t)tb * CN + (size_t)n * CC + h * 32 + d0;
#pragma unroll
        for (int j = 0; j < 8; j += 2) {
            __nv_bfloat162 p2;
            p2.x = __float2bfloat16((oa[j] >= 8.0f) ? 1.f : 0.f);
            p2.y = __float2bfloat16((oa[j + 1] >= 8.0f) ? 1.f : 0.f);
            *(__nv_bfloat162*)(op + j) = p2;
        }
        __syncthreads();
    }
}

// ---------------------------------------------------------------------------
// Gather spikes into temporal layout: dst[((n*B+b)*H+h)*320 + t*32 + e]
// ---------------------------------------------------------------------------
__global__ void __launch_bounds__(256) k_gather_temporal() {
    const int bx = blockIdx.x;
    const int which = bx / 5760;
    const int r = bx - which * 5760;
    const int ntile = r % 12;
    const int tbh = r / 12;
    const int tb = tbh / 12;
    const int h = tbh - tb * 12;
    const int t = tb / BB;
    const int b = tb - t * BB;

    const float* srcbase = (which == 0) ? g_q : (which == 1) ? g_k : g_v;
    float* dst = (which == 0) ? g_tq : (which == 1) ? g_tk : g_tv;
    const float* src = srcbase + (size_t)tb * CN + (size_t)h * 32 * NN + ntile * 32;

    __shared__ float tile[32][33];
    const int tid = threadIdx.x;
#pragma unroll
    for (int i = 0; i < 4; ++i) {
        int idx = tid + i * 256;
        int ee = idx >> 5, nn = idx & 31;
        tile[ee][nn] = src[(size_t)ee * NN + nn];
    }
    __syncthreads();
#pragma unroll
    for (int i = 0; i < 4; ++i) {
        int idx = tid + i * 256;
        int nn = idx >> 5, ee = idx & 31;
        int n = ntile * 32 + nn;
        dst[((size_t)(n * BB + b) * HH + h) * 320 + t * 32 + ee] = tile[ee][nn];
    }
}

// ---------------------------------------------------------------------------
// Temporal attention per (n,b,h); writes bf16 spikes to g_osT through the
// torch reshape shuffle flat = h*320+t*32+dd -> (t',c').
// ---------------------------------------------------------------------------
__global__ void __launch_bounds__(256) k_temporal_attn() {
    __shared__ float qs[8][321];
    __shared__ float ks2[8][321];
    __shared__ float vs2[8][321];
    __shared__ float at[8][112];

    const int wid = threadIdx.x >> 5;
    const int lane = threadIdx.x & 31;
    const int nbh = blockIdx.x * 8 + wid;
    const int h = nbh % HH;
    const int nb = nbh / HH;
    const int b = nb % BB;
    const int n = nb / BB;

    const float* qg = g_tq + (size_t)nbh * 320;
    const float* kg = g_tk + (size_t)nbh * 320;
    const float* vg = g_tv + (size_t)nbh * 320;

#pragma unroll
    for (int i = 0; i < TT; ++i) {
        qs[wid][lane * TT + i] = qg[i * 32 + lane];
        ks2[wid][lane * TT + i] = kg[i * 32 + lane];
        vs2[wid][i * 32 + lane] = vg[i * 32 + lane];
    }
    __syncwarp();

    for (int ii = lane; ii < 100; ii += 32) {
        int t = ii / 10, s = ii - t * 10;
        float acc = 0.f;
#pragma unroll
        for (int ee = 0; ee < 32; ++ee)
            acc = fmaf(qs[wid][ee * TT + t], ks2[wid][ee * TT + s], acc);
        at[wid][ii] = acc;
    }
    __syncwarp();

#pragma unroll
    for (int t = 0; t < TT; ++t) {
        float acc = 0.f;
#pragma unroll
        for (int s = 0; s < TT; ++s)
            acc = fmaf(at[wid][t * 10 + s], vs2[wid][s * 32 + lane], acc);
        float sp = (acc >= 8.0f) ? 1.0f : 0.0f;
        int flat = h * 320 + t * 32 + lane;
        int tp = flat / 384;
        int cp = flat - tp * 384;
        g_osT[(size_t)(tp * BB + b) * CN + (size_t)n * CC + cp] = __float2bfloat16(sp);
    }
}

// ---------------------------------------------------------------------------
// reductions + outer product
// ---------------------------------------------------------------------------
__global__ void __launch_bounds__(256) k_reduce_a() {
    const int row = blockIdx.x * 8 + (threadIdx.x >> 5);
    const int lane = threadIdx.x & 31;
    const float* p = g_a + (size_t)row * NN;
    float s = 0.f;
#pragma unroll
    for (int i = lane; i < NN; i += 32) s += p[i];
#pragma unroll
    for (int o = 16; o; o >>= 1) s += __shfl_xor_sync(0xffffffffu, s, o);
    if (lane == 0) g_ared[row] = s / (float)NN;
}

__global__ void __launch_bounds__(256) k_reduce_b() {
    const int i = blockIdx.x * 256 + threadIdx.x;
    float s = 0.f;
#pragma unroll
    for (int t = 0; t < TT; ++t) s += g_a[(size_t)t * BCN + i];
    g_bred[i] = s / (float)TT;
}

__global__ void __launch_bounds__(256) k_outer(float* __restrict__ out) {
    const int i = blockIdx.x * 256 + threadIdx.x;
    const int n = i % NN;
    const int rest = i / NN;
    const int c = rest % CC;
    const int tb = rest / CC;
    const int b = tb % BB;
    out[i] = g_ared[tb * CC + c] * g_bred[((size_t)b * CC + c) * NN + n];
}

// ---------------------------------------------------------------------------
extern "C" void kernel_launch(void* const* d_in, const int* in_sizes, int n_in,
                              void* d_out, int out_size)
{
    const float* x   = (const float*)d_in[0];
    const float* y   = (const float*)d_in[1];
    const float* sW  = (const float*)d_in[2];
    const float* sg  = (const float*)d_in[3];
    const float* sb  = (const float*)d_in[4];
    const float* tW  = (const float*)d_in[5];
    const float* tg  = (const float*)d_in[6];
    const float* tbn = (const float*)d_in[7];
    float* out = (float*)d_out;

    cudaFuncSetAttribute(k_qkv_tc, cudaFuncAttributeMaxDynamicSharedMemorySize, SMEM_QKV);
    cudaFuncSetAttribute(k_final_tc, cudaFuncAttributeMaxDynamicSharedMemorySize, SMEM_FIN);

    // precompute bf16 splits (W: 8 mats; X: x,y transposed)
    k_split_w<<<4608, 256>>>(sW, tW);
    k_split_xy<<<11520, 256>>>(x, y);

    dim3 gq(3, 3, 120), gf(3, 3, 40);

    // ---- spatial path ----
    k_qkv_tc<<<gq, 256, SMEM_QKV>>>(sg, sb, 0);
    k_spatial_attn<<<TT * BB * HH, 256>>>();
    k_final_tc<<<gf, 256, SMEM_FIN>>>(sg, sb, 0);
    k_reduce_a<<<(TT * BB * CC) / 8, 256>>>();

    // ---- temporal path ----
    k_qkv_tc<<<gq, 256, SMEM_QKV>>>(tg, tbn, 1);
    k_gather_temporal<<<3 * 480 * 12, 256>>>();
    k_temporal_attn<<<(NN * BB * HH) / 8, 256>>>();
    k_final_tc<<<gf, 256, SMEM_FIN>>>(tg, tbn, 1);
    k_reduce_b<<<BCN / 256, 256>>>();

    // ---- combine ----
    k_outer<<<TBCN / 256, 256>>>(out);
}

// round 6
// speedup vs baseline: 1.3066x; 1.2345x over previous
#include <cuda_runtime.h>
#include <cuda_bf16.h>
#include <cstdint>

// ---------------------------------------------------------------------------
// Spikformer spatial+temporal SSA — bf16 mma.sync, cp.async double-buffered.
//  - LIF outputs exactly binary; thresholds exact (>=2 conv, >=8 attention).
//  - fp32 = 3x bf16 split (exact); qkv GEMM = 6 bf16 term-pairs (fp32-exact),
//    final conv (binary B) = 3 term-pairs.
// ---------------------------------------------------------------------------

#define TT 10
#define BB 4
#define CC 384
#define NN 384
#define HH 12
#define CN (CC * NN)             // 147456
#define TBCN (TT * BB * CC * NN) // 5898240
#define BCN (BB * CC * NN)       // 589824

// scratch
__device__ __align__(128) float g_q[TBCN];   // spatial q spikes [tb][c][n]
__device__ __align__(128) float g_k[TBCN];
__device__ __align__(128) float g_v[TBCN];
__device__ __align__(128) float g_pq[TBCN];  // temporal proj spikes [tb][c][n]
__device__ __align__(128) float g_pk[TBCN];
__device__ __align__(128) float g_pv[TBCN];
__device__ __align__(128) float g_a[TBCN];   // temporal final spikes
__device__ __align__(128) float g_tq[TBCN];  // temporal gathered [(n*B+b)*H+h][t*32+e]
__device__ __align__(128) float g_tk[TBCN];
__device__ __align__(128) float g_tv[TBCN];
__device__ __align__(128) float g_M[480 * 1024];               // spatial k^T v
__device__ __align__(128) __nv_bfloat16 g_osT[TBCN];           // [tb][n][c] spikes
__device__ __align__(128) __nv_bfloat16 g_Wc[8 * 3 * CN];      // [mat][comp][o][c]
__device__ __align__(128) __nv_bfloat16 g_XT[2 * 3 * 40 * CN]; // [sel][comp][tb][n][c]
__device__ float g_ared[TT * BB * CC]; // raw row sums (spatial)
__device__ float g_bred[BCN];

__device__ __forceinline__ uint32_t smem_u32(const void* p) {
    uint32_t a;
    asm("{ .reg .u64 t; cvta.to.shared.u64 t, %1; cvt.u32.u64 %0, t; }"
        : "=r"(a) : "l"(p));
    return a;
}

__device__ __forceinline__ void ldsm_x4(uint32_t addr, uint32_t& r0, uint32_t& r1,
                                        uint32_t& r2, uint32_t& r3) {
    asm volatile("ldmatrix.sync.aligned.m8n8.x4.shared.b16 {%0,%1,%2,%3}, [%4];"
                 : "=r"(r0), "=r"(r1), "=r"(r2), "=r"(r3) : "r"(addr));
}

__device__ __forceinline__ void mma_bf16(float* c, uint32_t a0, uint32_t a1,
                                         uint32_t a2, uint32_t a3,
                                         uint32_t b0, uint32_t b1) {
    asm volatile(
        "mma.sync.aligned.m16n8k16.row.col.f32.bf16.bf16.f32 "
        "{%0,%1,%2,%3}, {%4,%5,%6,%7}, {%8,%9}, {%0,%1,%2,%3};"
        : "+f"(c[0]), "+f"(c[1]), "+f"(c[2]), "+f"(c[3])
        : "r"(a0), "r"(a1), "r"(a2), "r"(a3), "r"(b0), "r"(b1));
}

__device__ __forceinline__ uint32_t swz64(uint32_t off) {
    return off ^ ((off >> 3) & 0x30);
}

__device__ __forceinline__ void cp16(uint32_t dst, const void* src) {
    asm volatile("cp.async.cg.shared.global [%0], [%1], 16;" :: "r"(dst), "l"(src));
}

#define SMEM_QKV 99328
#define SMEM_FIN 66560

// ---------------------------------------------------------------------------
// fp32 -> 3x bf16 exact split precompute
// ---------------------------------------------------------------------------
__device__ __forceinline__ void split3(float x, __nv_bfloat16& a, __nv_bfloat16& b,
                                       __nv_bfloat16& c) {
    a = __float2bfloat16(x);
    float r = x - __bfloat162float(a);
    b = __float2bfloat16(r);
    float r2 = r - __bfloat162float(b);
    c = __float2bfloat16(r2);
}

__global__ void __launch_bounds__(256) k_split_w(const float* __restrict__ sW,
                                                 const float* __restrict__ tW) {
    int i = blockIdx.x * 256 + threadIdx.x;
    float w = (i < 4 * CN) ? sW[i] : tW[i - 4 * CN];
    int m = i / CN, e = i - m * CN;
    __nv_bfloat16 c1, c2, c3;
    split3(w, c1, c2, c3);
    size_t base = (size_t)m * 3 * CN + e;
    g_Wc[base] = c1;
    g_Wc[base + CN] = c2;
    g_Wc[base + 2 * CN] = c3;
}

__global__ void __launch_bounds__(256) k_split_xy(const float* __restrict__ x,
                                                  const float* __restrict__ y) {
    __shared__ float t[32][33];
    int bx = blockIdx.x;
    int sel = bx / 5760;
    int r = bx - sel * 5760;
    int tb = r / 144, tl = r - tb * 144;
    int ct = tl / 12, nt = tl - ct * 12;
    const float* src = (sel ? y : x) + (size_t)tb * CN + (size_t)(ct * 32) * NN + nt * 32;
    int tid = threadIdx.x;
#pragma unroll
    for (int i = 0; i < 4; ++i) {
        int idx = tid + i * 256;
        int cl = idx >> 5, nl = idx & 31;
        t[cl][nl] = src[(size_t)cl * NN + nl];
    }
    __syncthreads();
#pragma unroll
    for (int i = 0; i < 4; ++i) {
        int idx = tid + i * 256;
        int nl = idx >> 5, cl = idx & 31;
        __nv_bfloat16 c1, c2, c3;
        split3(t[cl][nl], c1, c2, c3);
        size_t base = ((size_t)(sel * 3) * 40 + tb) * CN + (size_t)(nt * 32 + nl) * CC + ct * 32 + cl;
        g_XT[base] = c1;
        g_XT[base + (size_t)40 * CN] = c2;
        g_XT[base + (size_t)80 * CN] = c3;
    }
}

__global__ void __launch_bounds__(256) k_zero_ared() {
    int i = blockIdx.x * 256 + threadIdx.x;
    if (i < TT * BB * CC) g_ared[i] = 0.0f;
}

// ---------------------------------------------------------------------------
// cp.async double-buffered tensor-core GEMM tile.
// D[128,128] = sum_pairs A_pa[128,384] * B_pb[128,384]^T  (both K-major)
// 12 stages of K=32, SMEM tiles 128x32 bf16 with SW64 swizzle.
// SUMA: fuse row-sum (spatial mean) into epilogue via atomics (Ob = sum base
// indexed by CHANNEL row), skip spike store. o0 is always the channel origin.
// ---------------------------------------------------------------------------
template <int NBC, bool SUMA>
__device__ __forceinline__ void tc_gemm_body(
    const __nv_bfloat16* __restrict__ A0,
    const __nv_bfloat16* __restrict__ B0, size_t bcs,
    const float* __restrict__ gs, const float* __restrict__ bs,
    float* __restrict__ Ob, int o0, int n0)
{
    constexpr int NC = 3 + NBC;
    constexpr uint32_t STAGE = NC * 8192u;
    extern __shared__ char smem_raw[];
    const uint32_t ab = (smem_u32(smem_raw) + 1023u) & ~1023u;
    const int tid = threadIdx.x;
    const int lane = tid & 31;
    const int wid = tid >> 5;
    const int wm = (wid >> 2) * 64;
    const int wn = (wid & 3) * 32;

    float acc[4][4][4];
#pragma unroll
    for (int mi = 0; mi < 4; ++mi)
#pragma unroll
        for (int ni = 0; ni < 4; ++ni)
#pragma unroll
            for (int r = 0; r < 4; ++r) acc[mi][ni][r] = 0.0f;

    const int a_row_l = lane & 15;
    const int a_ch = (lane >> 4) << 4;
    const int b_row_l = ((lane >> 4) & 1) * 8 + (lane & 7);
    const int b_ch = ((lane >> 3) & 1) << 4;

    auto load_stage = [&](int s, uint32_t buf) {
#pragma unroll
        for (int i = 0; i < NC * 2; ++i) {
            int idx = tid + i * 256;
            int comp = idx >> 9;
            int rem = idx & 511;
            int row = rem >> 2, ch = rem & 3;
            const __nv_bfloat16* g =
                (comp < 3) ? (A0 + (size_t)comp * CN) : (B0 + (size_t)(comp - 3) * bcs);
            g += (size_t)row * CC + s * 32 + ch * 8;
            uint32_t d = buf + comp * 8192 + swz64((uint32_t)(row * 64 + ch * 16));
            cp16(d, g);
        }
        asm volatile("cp.async.commit_group;" ::: "memory");
    };

    load_stage(0, ab);
    for (int s = 0; s < 12; ++s) {
        const uint32_t cur = ab + (uint32_t)(s & 1) * STAGE;
        if (s < 11) {
            load_stage(s + 1, ab + (uint32_t)((s + 1) & 1) * STAGE);
            asm volatile("cp.async.wait_group 1;" ::: "memory");
        } else {
            asm volatile("cp.async.wait_group 0;" ::: "memory");
        }
        __syncthreads();

        const int npairs = (NBC == 3) ? 6 : 3;
#pragma unroll
        for (int p = 0; p < 6; ++p) {
            if (p >= npairs) break;
            int pa, pb;
            if (NBC == 3) {
                const int PA[6] = {0, 0, 1, 0, 1, 2};
                const int PB[6] = {0, 1, 0, 2, 1, 0};
                pa = PA[p]; pb = PB[p];
            } else {
                pa = p; pb = 0;
            }
            const uint32_t abase = cur + pa * 8192;
            const uint32_t bbase = cur + (3 + pb) * 8192;
#pragma unroll
            for (int ks = 0; ks < 2; ++ks) {
                uint32_t afr[4][4];
#pragma unroll
                for (int mi = 0; mi < 4; ++mi) {
                    int row = wm + mi * 16 + a_row_l;
                    uint32_t off = (uint32_t)(row * 64 + ks * 32 + a_ch);
                    ldsm_x4(abase + swz64(off), afr[mi][0], afr[mi][1], afr[mi][2], afr[mi][3]);
                }
                uint32_t bfr[4][2];
#pragma unroll
                for (int bi = 0; bi < 2; ++bi) {
                    int row = wn + bi * 16 + b_row_l;
                    uint32_t off = (uint32_t)(row * 64 + ks * 32 + b_ch);
                    uint32_t r0, r1, r2, r3;
                    ldsm_x4(bbase + swz64(off), r0, r1, r2, r3);
                    bfr[bi * 2][0] = r0; bfr[bi * 2][1] = r1;
                    bfr[bi * 2 + 1][0] = r2; bfr[bi * 2 + 1][1] = r3;
                }
#pragma unroll
                for (int mi = 0; mi < 4; ++mi)
#pragma unroll
                    for (int ni = 0; ni < 4; ++ni)
                        mma_bf16(acc[mi][ni], afr[mi][0], afr[mi][1], afr[mi][2],
                                 afr[mi][3], bfr[ni][0], bfr[ni][1]);
            }
        }
        __syncthreads();
    }

    // epilogue: BN + spike. row = channel index (always in [0,384)).
#pragma unroll
    for (int mi = 0; mi < 4; ++mi) {
#pragma unroll
        for (int half = 0; half < 2; ++half) {
            const int row = o0 + wm + mi * 16 + half * 8 + (lane >> 2);
            const float gv = gs[row];
            const float bv = bs[row];
            float vals[8];
#pragma unroll
            for (int ni = 0; ni < 4; ++ni) {
                vals[ni * 2 + 0] = (fmaf(acc[mi][ni][half * 2 + 0], gv, bv) >= 2.0f) ? 1.f : 0.f;
                vals[ni * 2 + 1] = (fmaf(acc[mi][ni][half * 2 + 1], gv, bv) >= 2.0f) ? 1.f : 0.f;
            }
            if (SUMA) {
                // Ob = row-sum base (g_ared + tb*CC), indexed by channel row
                float s = 0.f;
#pragma unroll
                for (int j = 0; j < 8; ++j) s += vals[j];
                s += __shfl_xor_sync(0xffffffffu, s, 1);
                s += __shfl_xor_sync(0xffffffffu, s, 2);
                if ((lane & 3) == 0) atomicAdd(&Ob[row], s);
            } else {
                float* dst = Ob + (size_t)row * NN + n0 + wn + (lane & 3) * 2;
#pragma unroll
                for (int ni = 0; ni < 4; ++ni) {
                    float2 w;
                    w.x = vals[ni * 2 + 0];
                    w.y = vals[ni * 2 + 1];
                    *(float2*)(dst + ni * 8) = w;
                }
            }
        }
    }
}

// combined qkv for BOTH paths: grid (3,3,240): z -> pj = z/40 (path*3+j), tb
__global__ void __launch_bounds__(256, 2) k_qkv_all(
    const float* __restrict__ sg, const float* __restrict__ sb,
    const float* __restrict__ tg, const float* __restrict__ tb_)
{
    int z = blockIdx.z;
    int pj = z / 40, tb = z - pj * 40;
    int path = pj / 3, j = pj - path * 3;
    int o0 = blockIdx.y * 128, n0 = blockIdx.x * 128;
    const __nv_bfloat16* A0 = g_Wc + (size_t)((path * 4 + j) * 3) * CN + (size_t)o0 * CC;
    int sel = (j == 0) ? 0 : 1;
    const __nv_bfloat16* B0 = g_XT + ((size_t)(sel * 3) * 40 + tb) * CN + (size_t)n0 * CC;
    float* Ob;
    if (path == 0) Ob = (j == 0) ? g_q : (j == 1) ? g_k : g_v;
    else           Ob = (j == 0) ? g_pq : (j == 1) ? g_pk : g_pv;
    const float* gs = (path == 0) ? sg : tg;
    const float* bs = (path == 0) ? sb : tb_;
    tc_gemm_body<3, false>(A0, B0, (size_t)40 * CN, gs + j * CC, bs + j * CC,
                           Ob + (size_t)tb * CN, o0, n0);
}

// spatial final conv with fused row-mean (atomics into g_ared), grid (3,3,40)
__global__ void __launch_bounds__(256, 2) k_final_s(const float* __restrict__ g4,
                                                    const float* __restrict__ b4) {
    int tb = blockIdx.z;
    int o0 = blockIdx.y * 128, n0 = blockIdx.x * 128;
    const __nv_bfloat16* A0 = g_Wc + (size_t)(3 * 3) * CN + (size_t)o0 * CC;
    const __nv_bfloat16* B0 = g_osT + (size_t)tb * CN + (size_t)n0 * CC;
    tc_gemm_body<1, true>(A0, B0, 0, g4 + 3 * CC, b4 + 3 * CC,
                          g_ared + (size_t)tb * CC, o0, n0);
}

// temporal final conv -> g_a, grid (3,3,40)
__global__ void __launch_bounds__(256, 2) k_final_t(const float* __restrict__ g4,
                                                    const float* __restrict__ b4) {
    int tb = blockIdx.z;
    int o0 = blockIdx.y * 128, n0 = blockIdx.x * 128;
    const __nv_bfloat16* A0 = g_Wc + (size_t)(7 * 3) * CN + (size_t)o0 * CC;
    const __nv_bfloat16* B0 = g_osT + (size_t)tb * CN + (size_t)n0 * CC;
    tc_gemm_body<1, false>(A0, B0, 0, g4 + 3 * CC, b4 + 3 * CC,
                           g_a + (size_t)tb * CN, o0, n0);
}

// ---------------------------------------------------------------------------
// Spatial attention: phase 1 -> M = k^T v per (t,b,h), stored to g_M.
// ---------------------------------------------------------------------------
__global__ void __launch_bounds__(256) k_kvM() {
    __shared__ float ks[64][33];
    __shared__ float vs[64][33];

    const int blk = blockIdx.x;
    const int tb = blk / HH;
    const int h = blk - tb * HH;
    const size_t base = (size_t)tb * CN + (size_t)h * 32 * NN;
    const float* kb = g_k + base;
    const float* vb = g_v + base;
    const int tid = threadIdx.x;

    const int e = tid >> 3;
    const int dd0 = (tid & 7) << 2;
    float mc0 = 0.f, mc1 = 0.f, mc2 = 0.f, mc3 = 0.f;
    for (int m0 = 0; m0 < NN; m0 += 64) {
#pragma unroll
        for (int i = 0; i < 8; ++i) {
            int idx = tid + i * 256;
            int ee = idx >> 6, mm = idx & 63;
            ks[mm][ee] = kb[(size_t)ee * NN + m0 + mm];
            vs[mm][ee] = vb[(size_t)ee * NN + m0 + mm];
        }
        __syncthreads();
#pragma unroll 8
        for (int mm = 0; mm < 64; ++mm) {
            float kv = ks[mm][e];
            mc0 = fmaf(kv, vs[mm][dd0 + 0], mc0);
            mc1 = fmaf(kv, vs[mm][dd0 + 1], mc1);
            mc2 = fmaf(kv, vs[mm][dd0 + 2], mc2);
            mc3 = fmaf(kv, vs[mm][dd0 + 3], mc3);
        }
        __syncthreads();
    }
    float* Mp = g_M + (size_t)blk * 1024 + e * 32 + dd0;
    Mp[0] = mc0; Mp[1] = mc1; Mp[2] = mc2; Mp[3] = mc3;
}

// Phase 2: o = q M, spike >= 8, write transposed bf16 into g_osT[tb][n][c].
// grid (480*3): blk -> (tbh, ntile of 128). 256 threads: (n 0..127, dhalf 0..1)
__global__ void __launch_bounds__(256) k_qM() {
    __shared__ float Ms[32][32];
    const int blk = blockIdx.x;
    const int tbh = blk / 3;
    const int nt = blk - tbh * 3;
    const int tb = tbh / HH;
    const int h = tbh - tb * HH;
    const int tid = threadIdx.x;

#pragma unroll
    for (int i = 0; i < 4; ++i) {
        int idx = tid + i * 256;
        Ms[idx >> 5][idx & 31] = g_M[(size_t)tbh * 1024 + idx];
    }
    __syncthreads();

    const int n = nt * 128 + (tid & 127);
    const int d0 = (tid >> 7) * 16;
    const float* qb = g_q + (size_t)tb * CN + (size_t)h * 32 * NN + n;

    float acc[16];
#pragma unroll
    for (int j = 0; j < 16; ++j) acc[j] = 0.f;
#pragma unroll
    for (int e = 0; e < 32; ++e) {
        float qv = qb[(size_t)e * NN];
#pragma unroll
        for (int j = 0; j < 16; ++j) acc[j] = fmaf(qv, Ms[e][d0 + j], acc[j]);
    }
    __nv_bfloat16* op = g_osT + (size_t)tb * CN + (size_t)n * CC + h * 32 + d0;
#pragma unroll
    for (int j = 0; j < 16; j += 2) {
        __nv_bfloat162 p2;
        p2.x = __float2bfloat16((acc[j] >= 8.0f) ? 1.f : 0.f);
        p2.y = __float2bfloat16((acc[j + 1] >= 8.0f) ? 1.f : 0.f);
        *(__nv_bfloat162*)(op + j) = p2;
    }
}

// ---------------------------------------------------------------------------
// Gather temporal proj spikes: dst[((n*B+b)*H+h)*320 + t*32 + e]
// ---------------------------------------------------------------------------
__global__ void __launch_bounds__(256) k_gather_temporal() {
    const int bx = blockIdx.x;
    const int which = bx / 5760;
    const int r = bx - which * 5760;
    const int ntile = r % 12;
    const int tbh = r / 12;
    const int tb = tbh / 12;
    const int h = tbh - tb * 12;
    const int t = tb / BB;
    const int b = tb - t * BB;

    const float* srcbase = (which == 0) ? g_pq : (which == 1) ? g_pk : g_pv;
    float* dst = (which == 0) ? g_tq : (which == 1) ? g_tk : g_tv;
    const float* src = srcbase + (size_t)tb * CN + (size_t)h * 32 * NN + ntile * 32;

    __shared__ float tile[32][33];
    const int tid = threadIdx.x;
#pragma unroll
    for (int i = 0; i < 4; ++i) {
        int idx = tid + i * 256;
        int ee = idx >> 5, nn = idx & 31;
        tile[ee][nn] = src[(size_t)ee * NN + nn];
    }
    __syncthreads();
#pragma unroll
    for (int i = 0; i < 4; ++i) {
        int idx = tid + i * 256;
        int nn = idx >> 5, ee = idx & 31;
        int n = ntile * 32 + nn;
        dst[((size_t)(n * BB + b) * HH + h) * 320 + t * 32 + ee] = tile[ee][nn];
    }
}

// ---------------------------------------------------------------------------
// Temporal attention per (n,b,h); writes bf16 spikes to g_osT via the torch
// reshape shuffle flat = h*320+t*32+dd -> (t',c').
// ---------------------------------------------------------------------------
__global__ void __launch_bounds__(256) k_temporal_attn() {
    __shared__ float qs[8][321];
    __shared__ float ks2[8][321];
    __shared__ float vs2[8][321];
    __shared__ float at[8][112];

    const int wid = threadIdx.x >> 5;
    const int lane = threadIdx.x & 31;
    const int nbh = blockIdx.x * 8 + wid;
    const int h = nbh % HH;
    const int nb = nbh / HH;
    const int b = nb % BB;
    const int n = nb / BB;

    const float* qg = g_tq + (size_t)nbh * 320;
    const float* kg = g_tk + (size_t)nbh * 320;
    const float* vg = g_tv + (size_t)nbh * 320;

#pragma unroll
    for (int i = 0; i < TT; ++i) {
        qs[wid][lane * TT + i] = qg[i * 32 + lane];
        ks2[wid][lane * TT + i] = kg[i * 32 + lane];
        vs2[wid][i * 32 + lane] = vg[i * 32 + lane];
    }
    __syncwarp();

    for (int ii = lane; ii < 100; ii += 32) {
        int t = ii / 10, s = ii - t * 10;
        float acc = 0.f;
#pragma unroll
        for (int ee = 0; ee < 32; ++ee)
            acc = fmaf(qs[wid][ee * TT + t], ks2[wid][ee * TT + s], acc);
        at[wid][ii] = acc;
    }
    __syncwarp();

#pragma unroll
    for (int t = 0; t < TT; ++t) {
        float acc = 0.f;
#pragma unroll
        for (int s = 0; s < TT; ++s)
            acc = fmaf(at[wid][t * 10 + s], vs2[wid][s * 32 + lane], acc);
        float sp = (acc >= 8.0f) ? 1.0f : 0.0f;
        int flat = h * 320 + t * 32 + lane;
        int tp = flat / 384;
        int cp = flat - tp * 384;
        g_osT[(size_t)(tp * BB + b) * CN + (size_t)n * CC + cp] = __float2bfloat16(sp);
    }
}

// ---------------------------------------------------------------------------
// reductions + outer product
// ---------------------------------------------------------------------------
__global__ void __launch_bounds__(256) k_reduce_b() {
    const int i = blockIdx.x * 256 + threadIdx.x;
    float s = 0.f;
#pragma unroll
    for (int t = 0; t < TT; ++t) s += g_a[(size_t)t * BCN + i];
    g_bred[i] = s / (float)TT;
}

__global__ void __launch_bounds__(256) k_outer(float* __restrict__ out) { // 5760 blocks
    const int i = blockIdx.x * 256 + threadIdx.x;
    const int e = i * 4;
    const int n = e % NN;
    const int rest = e / NN;
    const int c = rest % CC;
    const int tb = rest / CC;
    const int b = tb % BB;
    const float a = g_ared[tb * CC + c] * (1.0f / 384.0f);
    const float* bp = &g_bred[((size_t)b * CC + c) * NN + n];
    float4 w;
    w.x = a * bp[0]; w.y = a * bp[1]; w.z = a * bp[2]; w.w = a * bp[3];
    *(float4*)(out + e) = w;
}

// ---------------------------------------------------------------------------
extern "C" void kernel_launch(void* const* d_in, const int* in_sizes, int n_in,
                              void* d_out, int out_size)
{
    const float* x   = (const float*)d_in[0];
    const float* y   = (const float*)d_in[1];
    const float* sW  = (const float*)d_in[2];
    const float* sg  = (const float*)d_in[3];
    const float* sb  = (const float*)d_in[4];
    const float* tW  = (const float*)d_in[5];
    const float* tg  = (const float*)d_in[6];
    const float* tbn = (const float*)d_in[7];
    float* out = (float*)d_out;

    cudaFuncSetAttribute(k_qkv_all, cudaFuncAttributeMaxDynamicSharedMemorySize, SMEM_QKV);
    cudaFuncSetAttribute(k_final_s, cudaFuncAttributeMaxDynamicSharedMemorySize, SMEM_FIN);
    cudaFuncSetAttribute(k_final_t, cudaFuncAttributeMaxDynamicSharedMemorySize, SMEM_FIN);

    // precompute splits
    k_split_w<<<4608, 256>>>(sW, tW);
    k_split_xy<<<11520, 256>>>(x, y);
    k_zero_ared<<<60, 256>>>();

    // all 6 qkv projections (both paths) in one launch
    k_qkv_all<<<dim3(3, 3, 240), 256, SMEM_QKV>>>(sg, sb, tg, tbn);

    // ---- spatial path ----
    k_kvM<<<480, 256>>>();
    k_qM<<<480 * 3, 256>>>();
    k_final_s<<<dim3(3, 3, 40), 256, SMEM_FIN>>>(sg, sb); // fused row-mean

    // ---- temporal path ----
    k_gather_temporal<<<3 * 5760, 256>>>();
    k_temporal_attn<<<(NN * BB * HH) / 8, 256>>>();
    k_final_t<<<dim3(3, 3, 40), 256, SMEM_FIN>>>(tg, tbn);
    k_reduce_b<<<BCN / 256, 256>>>();

    // ---- combine ----
    k_outer<<<TBCN / 1024, 256>>>(out);
}

// round 8
// speedup vs baseline: 1.7298x; 1.3239x over previous
#include <cuda_runtime.h>
#include <cuda_bf16.h>
#include <cstdint>

// ---------------------------------------------------------------------------
// Spikformer spatial+temporal SSA — bf16 mma.sync, cp.async double-buffered,
// register-cached B fragments, persistent qkv grid.
//  - LIF outputs exactly binary; thresholds exact (>=2 conv, >=8 attention).
//  - fp32 = 3x bf16 split (exact); qkv GEMM = 6 bf16 term-pairs (fp32-exact),
//    final conv (binary B) = 3 term-pairs.
// ---------------------------------------------------------------------------

#define TT 10
#define BB 4
#define CC 384
#define NN 384
#define HH 12
#define CN (CC * NN)             // 147456
#define TBCN (TT * BB * CC * NN) // 5898240
#define BCN (BB * CC * NN)       // 589824

// scratch
__device__ __align__(128) float g_q[TBCN];   // spatial q spikes [tb][c][n]
__device__ __align__(128) float g_k[TBCN];
__device__ __align__(128) float g_v[TBCN];
__device__ __align__(128) float g_pq[TBCN];  // temporal proj spikes [tb][c][n]
__device__ __align__(128) float g_pk[TBCN];
__device__ __align__(128) float g_pv[TBCN];
__device__ __align__(128) float g_a[TBCN];   // temporal final spikes
__device__ __align__(128) float g_tq[TBCN];  // temporal gathered [(n*B+b)*H+h][t*32+e]
__device__ __align__(128) float g_tk[TBCN];
__device__ __align__(128) float g_tv[TBCN];
__device__ __align__(128) float g_M[480 * 1024];               // spatial k^T v
__device__ __align__(128) __nv_bfloat16 g_osT[TBCN];           // [tb][n][c] spikes
__device__ __align__(128) __nv_bfloat16 g_Wc[8 * 3 * CN];      // [mat][comp][o][c]
__device__ __align__(128) __nv_bfloat16 g_XT[2 * 3 * 40 * CN]; // [sel][comp][tb][n][c]
__device__ float g_ared[TT * BB * CC]; // raw row sums (spatial)
__device__ float g_bred[BCN];

__device__ __forceinline__ uint32_t smem_u32(const void* p) {
    uint32_t a;
    asm("{ .reg .u64 t; cvta.to.shared.u64 t, %1; cvt.u32.u64 %0, t; }"
        : "=r"(a) : "l"(p));
    return a;
}

__device__ __forceinline__ void ldsm_x4(uint32_t addr, uint32_t& r0, uint32_t& r1,
                                        uint32_t& r2, uint32_t& r3) {
    asm volatile("ldmatrix.sync.aligned.m8n8.x4.shared.b16 {%0,%1,%2,%3}, [%4];"
                 : "=r"(r0), "=r"(r1), "=r"(r2), "=r"(r3) : "r"(addr));
}

__device__ __forceinline__ void mma_bf16(float* c, const uint32_t* a,
                                         uint32_t b0, uint32_t b1) {
    asm volatile(
        "mma.sync.aligned.m16n8k16.row.col.f32.bf16.bf16.f32 "
        "{%0,%1,%2,%3}, {%4,%5,%6,%7}, {%8,%9}, {%0,%1,%2,%3};"
        : "+f"(c[0]), "+f"(c[1]), "+f"(c[2]), "+f"(c[3])
        : "r"(a[0]), "r"(a[1]), "r"(a[2]), "r"(a[3]), "r"(b0), "r"(b1));
}

__device__ __forceinline__ uint32_t swz64(uint32_t off) {
    return off ^ ((off >> 3) & 0x30);
}

__device__ __forceinline__ void cp16(uint32_t dst, const void* src) {
    asm volatile("cp.async.cg.shared.global [%0], [%1], 16;" :: "r"(dst), "l"(src));
}

#define SMEM_QKV 99328
#define SMEM_FIN 66560

// ---------------------------------------------------------------------------
// fp32 -> 3x bf16 exact split precompute
// ---------------------------------------------------------------------------
__device__ __forceinline__ void split3(float x, __nv_bfloat16& a, __nv_bfloat16& b,
                                       __nv_bfloat16& c) {
    a = __float2bfloat16(x);
    float r = x - __bfloat162float(a);
    b = __float2bfloat16(r);
    float r2 = r - __bfloat162float(b);
    c = __float2bfloat16(r2);
}

__global__ void __launch_bounds__(256) k_split_w(const float* __restrict__ sW,
                                                 const float* __restrict__ tW) {
    int i = blockIdx.x * 256 + threadIdx.x;
    float w = (i < 4 * CN) ? sW[i] : tW[i - 4 * CN];
    int m = i / CN, e = i - m * CN;
    __nv_bfloat16 c1, c2, c3;
    split3(w, c1, c2, c3);
    size_t base = (size_t)m * 3 * CN + e;
    g_Wc[base] = c1;
    g_Wc[base + CN] = c2;
    g_Wc[base + 2 * CN] = c3;
}

__global__ void __launch_bounds__(256) k_split_xy(const float* __restrict__ x,
                                                  const float* __restrict__ y) {
    __shared__ float t[32][33];
    int bx = blockIdx.x;
    int sel = bx / 5760;
    int r = bx - sel * 5760;
    int tb = r / 144, tl = r - tb * 144;
    int ct = tl / 12, nt = tl - ct * 12;
    const float* src = (sel ? y : x) + (size_t)tb * CN + (size_t)(ct * 32) * NN + nt * 32;
    int tid = threadIdx.x;
#pragma unroll
    for (int i = 0; i < 4; ++i) {
        int idx = tid + i * 256;
        int cl = idx >> 5, nl = idx & 31;
        t[cl][nl] = src[(size_t)cl * NN + nl];
    }
    __syncthreads();
#pragma unroll
    for (int i = 0; i < 4; ++i) {
        int idx = tid + i * 256;
        int nl = idx >> 5, cl = idx & 31;
        __nv_bfloat16 c1, c2, c3;
        split3(t[cl][nl], c1, c2, c3);
        size_t base = ((size_t)(sel * 3) * 40 + tb) * CN + (size_t)(nt * 32 + nl) * CC + ct * 32 + cl;
        g_XT[base] = c1;
        g_XT[base + (size_t)40 * CN] = c2;
        g_XT[base + (size_t)80 * CN] = c3;
    }
}

__global__ void __launch_bounds__(256) k_zero_ared() {
    int i = blockIdx.x * 256 + threadIdx.x;
    if (i < TT * BB * CC) g_ared[i] = 0.0f;
}

// ---------------------------------------------------------------------------
// cp.async double-buffered tensor-core GEMM tile, register-cached B frags.
// D[128,128] = sum_pairs A_pa[128,384] * B_pb[128,384]^T  (both K-major)
// 12 stages of K=32, SMEM tiles 128x32 bf16 with SW64 swizzle.
// suma: fuse row-sum into epilogue via atomics (Ob indexed by channel row).
// ---------------------------------------------------------------------------
template <int NBC>
__device__ __forceinline__ void tc_gemm_body(
    const __nv_bfloat16* __restrict__ A0,
    const __nv_bfloat16* __restrict__ B0, size_t bcs,
    const float* __restrict__ gs, const float* __restrict__ bs,
    float* __restrict__ Ob, int o0, int n0, bool suma)
{
    constexpr int NC = 3 + NBC;
    constexpr uint32_t STAGE = NC * 8192u;
    extern __shared__ char smem_raw[];
    const uint32_t ab = (smem_u32(smem_raw) + 1023u) & ~1023u;
    const int tid = threadIdx.x;
    const int lane = tid & 31;
    const int wid = tid >> 5;
    const int wm = (wid >> 2) * 64;
    const int wn = (wid & 3) * 32;

    float acc[4][4][4];
#pragma unroll
    for (int mi = 0; mi < 4; ++mi)
#pragma unroll
        for (int ni = 0; ni < 4; ++ni)
#pragma unroll
            for (int r = 0; r < 4; ++r) acc[mi][ni][r] = 0.0f;

    const int a_row_l = lane & 15;
    const int a_ch = (lane >> 4) << 4;
    const int b_row_l = ((lane >> 4) & 1) * 8 + (lane & 7);
    const int b_ch = ((lane >> 3) & 1) << 4;

    auto load_stage = [&](int s, uint32_t buf) {
#pragma unroll
        for (int i = 0; i < NC * 2; ++i) {
            int idx = tid + i * 256;
            int comp = idx >> 9;
            int rem = idx & 511;
            int row = rem >> 2, ch = rem & 3;
            const __nv_bfloat16* g =
                (comp < 3) ? (A0 + (size_t)comp * CN) : (B0 + (size_t)(comp - 3) * bcs);
            g += (size_t)row * CC + s * 32 + ch * 8;
            uint32_t d = buf + comp * 8192 + swz64((uint32_t)(row * 64 + ch * 16));
            cp16(d, g);
        }
        asm volatile("cp.async.commit_group;" ::: "memory");
    };

    // B-fragment loader: base -> 4 (n8,k16) frags packed as [4][2]
    auto load_bf = [&](uint32_t base, int ks, uint32_t bf[4][2]) {
#pragma unroll
        for (int bi = 0; bi < 2; ++bi) {
            int row = wn + bi * 16 + b_row_l;
            uint32_t off = (uint32_t)(row * 64 + ks * 32 + b_ch);
            uint32_t r0, r1, r2, r3;
            ldsm_x4(base + swz64(off), r0, r1, r2, r3);
            bf[bi * 2][0] = r0; bf[bi * 2][1] = r1;
            bf[bi * 2 + 1][0] = r2; bf[bi * 2 + 1][1] = r3;
        }
    };
    auto load_af = [&](uint32_t base, int ks, int mi, uint32_t* af) {
        int row = wm + mi * 16 + a_row_l;
        uint32_t off = (uint32_t)(row * 64 + ks * 32 + a_ch);
        ldsm_x4(base + swz64(off), af[0], af[1], af[2], af[3]);
    };

    load_stage(0, ab);
    for (int s = 0; s < 12; ++s) {
        const uint32_t cur = ab + (uint32_t)(s & 1) * STAGE;
        if (s < 11) {
            load_stage(s + 1, ab + (uint32_t)((s + 1) & 1) * STAGE);
            asm volatile("cp.async.wait_group 1;" ::: "memory");
        } else {
            asm volatile("cp.async.wait_group 0;" ::: "memory");
        }
        __syncthreads();

#pragma unroll
        for (int ks = 0; ks < 2; ++ks) {
            uint32_t b0[4][2];
            load_bf(cur + 3 * 8192, ks, b0); // pb=0, cached (used by all pa)
#pragma unroll
            for (int pa = 0; pa < 3; ++pa) {
                uint32_t afr[4][4];
#pragma unroll
                for (int mi = 0; mi < 4; ++mi) load_af(cur + pa * 8192, ks, mi, afr[mi]);
#pragma unroll
                for (int mi = 0; mi < 4; ++mi)
#pragma unroll
                    for (int ni = 0; ni < 4; ++ni)
                        mma_bf16(acc[mi][ni], afr[mi], b0[ni][0], b0[ni][1]);
                if (NBC == 3) {
                    if (pa < 2) { // pb=1 (pairs (0,1),(1,1))
                        uint32_t bt[4][2];
                        load_bf(cur + 4 * 8192, ks, bt);
#pragma unroll
                        for (int mi = 0; mi < 4; ++mi)
#pragma unroll
                            for (int ni = 0; ni < 4; ++ni)
                                mma_bf16(acc[mi][ni], afr[mi], bt[ni][0], bt[ni][1]);
                    }
                    if (pa == 0) { // pb=2 (pair (0,2))
                        uint32_t bt[4][2];
                        load_bf(cur + 5 * 8192, ks, bt);
#pragma unroll
                        for (int mi = 0; mi < 4; ++mi)
#pragma unroll
                            for (int ni = 0; ni < 4; ++ni)
                                mma_bf16(acc[mi][ni], afr[mi], bt[ni][0], bt[ni][1]);
                    }
                }
            }
        }
        __syncthreads();
    }

    // epilogue: BN + spike. row = channel index (always in [0,384)).
#pragma unroll
    for (int mi = 0; mi < 4; ++mi) {
#pragma unroll
        for (int half = 0; half < 2; ++half) {
            const int row = o0 + wm + mi * 16 + half * 8 + (lane >> 2);
            const float gv = gs[row];
            const float bv = bs[row];
            float vals[8];
#pragma unroll
            for (int ni = 0; ni < 4; ++ni) {
                vals[ni * 2 + 0] = (fmaf(acc[mi][ni][half * 2 + 0], gv, bv) >= 2.0f) ? 1.f : 0.f;
                vals[ni * 2 + 1] = (fmaf(acc[mi][ni][half * 2 + 1], gv, bv) >= 2.0f) ? 1.f : 0.f;
            }
            if (suma) {
                float sum = 0.f;
#pragma unroll
                for (int j = 0; j < 8; ++j) sum += vals[j];
                sum += __shfl_xor_sync(0xffffffffu, sum, 1);
                sum += __shfl_xor_sync(0xffffffffu, sum, 2);
                if ((lane & 3) == 0) atomicAdd(&Ob[row], sum);
            } else {
                float* dst = Ob + (size_t)row * NN + n0 + wn + (lane & 3) * 2;
#pragma unroll
                for (int ni = 0; ni < 4; ++ni) {
                    float2 w;
                    w.x = vals[ni * 2 + 0];
                    w.y = vals[ni * 2 + 1];
                    *(float2*)(dst + ni * 8) = w;
                }
            }
        }
    }
}

// Persistent qkv for BOTH paths: 2160 tiles over gridDim.x blocks.
// tile -> (nx, my, tb, j, path)
__global__ void __launch_bounds__(256, 2) k_qkv_all(
    const float* __restrict__ sg, const float* __restrict__ sb,
    const float* __restrict__ tg, const float* __restrict__ tb_)
{
    for (int tile = blockIdx.x; tile < 2160; tile += gridDim.x) {
        int nx = tile % 3;
        int rest = tile / 3;
        int my = rest % 3;
        int z = rest / 3;
        int pj = z / 40, tb = z - pj * 40;
        int path = pj / 3, j = pj - path * 3;
        int o0 = my * 128, n0 = nx * 128;
        const __nv_bfloat16* A0 = g_Wc + (size_t)((path * 4 + j) * 3) * CN + (size_t)o0 * CC;
        int sel = (j == 0) ? 0 : 1;
        const __nv_bfloat16* B0 = g_XT + ((size_t)(sel * 3) * 40 + tb) * CN + (size_t)n0 * CC;
        float* Ob;
        if (path == 0) Ob = (j == 0) ? g_q : (j == 1) ? g_k : g_v;
        else           Ob = (j == 0) ? g_pq : (j == 1) ? g_pk : g_pv;
        const float* gs = (path == 0) ? sg : tg;
        const float* bs = (path == 0) ? sb : tb_;
        tc_gemm_body<3>(A0, B0, (size_t)40 * CN, gs + j * CC, bs + j * CC,
                        Ob + (size_t)tb * CN, o0, n0, false);
    }
}

// merged final convs: grid (3,3,80); z<40: spatial (fused row-mean), else temporal
__global__ void __launch_bounds__(256, 2) k_final_all(
    const float* __restrict__ sg, const float* __restrict__ sb,
    const float* __restrict__ tg, const float* __restrict__ tb_)
{
    int z = blockIdx.z;
    int path = z / 40, tb = z - path * 40;
    int o0 = blockIdx.y * 128, n0 = blockIdx.x * 128;
    const __nv_bfloat16* A0 = g_Wc + (size_t)((path * 4 + 3) * 3) * CN + (size_t)o0 * CC;
    const __nv_bfloat16* B0 = g_osT + (size_t)tb * CN + (size_t)n0 * CC;
    const float* gs = (path == 0) ? sg : tg;
    const float* bs = (path == 0) ? sb : tb_;
    float* Ob = (path == 0) ? (g_ared + (size_t)tb * CC) : (g_a + (size_t)tb * CN);
    tc_gemm_body<1>(A0, B0, 0, gs + 3 * CC, bs + 3 * CC, Ob, o0, n0, path == 0);
}

// ---------------------------------------------------------------------------
// Spatial attention: phase 1 -> M = k^T v per (t,b,h), stored to g_M.
// ---------------------------------------------------------------------------
__global__ void __launch_bounds__(256) k_kvM() {
    __shared__ float ks[64][33];
    __shared__ float vs[64][33];

    const int blk = blockIdx.x;
    const int tb = blk / HH;
    const int h = blk - tb * HH;
    const size_t base = (size_t)tb * CN + (size_t)h * 32 * NN;
    const float* kb = g_k + base;
    const float* vb = g_v + base;
    const int tid = threadIdx.x;

    const int e = tid >> 3;
    const int dd0 = (tid & 7) << 2;
    float mc0 = 0.f, mc1 = 0.f, mc2 = 0.f, mc3 = 0.f;
    for (int m0 = 0; m0 < NN; m0 += 64) {
#pragma unroll
        for (int i = 0; i < 8; ++i) {
            int idx = tid + i * 256;
            int ee = idx >> 6, mm = idx & 63;
            ks[mm][ee] = kb[(size_t)ee * NN + m0 + mm];
            vs[mm][ee] = vb[(size_t)ee * NN + m0 + mm];
        }
        __syncthreads();
#pragma unroll 8
        for (int mm = 0; mm < 64; ++mm) {
            float kv = ks[mm][e];
            mc0 = fmaf(kv, vs[mm][dd0 + 0], mc0);
            mc1 = fmaf(kv, vs[mm][dd0 + 1], mc1);
            mc2 = fmaf(kv, vs[mm][dd0 + 2], mc2);
            mc3 = fmaf(kv, vs[mm][dd0 + 3], mc3);
        }
        __syncthreads();
    }
    float* Mp = g_M + (size_t)blk * 1024 + e * 32 + dd0;
    Mp[0] = mc0; Mp[1] = mc1; Mp[2] = mc2; Mp[3] = mc3;
}

// Phase 2: o = q M, spike >= 8, write transposed bf16 into g_osT[tb][n][c].
__global__ void __launch_bounds__(256) k_qM() {
    __shared__ float Ms[32][32];
    const int blk = blockIdx.x;
    const int tbh = blk / 3;
    const int nt = blk - tbh * 3;
    const int tb = tbh / HH;
    const int h = tbh - tb * HH;
    const int tid = threadIdx.x;

#pragma unroll
    for (int i = 0; i < 4; ++i) {
        int idx = tid + i * 256;
        Ms[idx >> 5][idx & 31] = g_M[(size_t)tbh * 1024 + idx];
    }
    __syncthreads();

    const int n = nt * 128 + (tid & 127);
    const int d0 = (tid >> 7) * 16;
    const float* qb = g_q + (size_t)tb * CN + (size_t)h * 32 * NN + n;

    float acc[16];
#pragma unroll
    for (int j = 0; j < 16; ++j) acc[j] = 0.f;
#pragma unroll
    for (int e = 0; e < 32; ++e) {
        float qv = qb[(size_t)e * NN];
#pragma unroll
        for (int j = 0; j < 16; ++j) acc[j] = fmaf(qv, Ms[e][d0 + j], acc[j]);
    }
    __nv_bfloat16* op = g_osT + (size_t)tb * CN + (size_t)n * CC + h * 32 + d0;
#pragma unroll
    for (int j = 0; j < 16; j += 2) {
        __nv_bfloat162 p2;
        p2.x = __float2bfloat16((acc[j] >= 8.0f) ? 1.f : 0.f);
        p2.y = __float2bfloat16((acc[j + 1] >= 8.0f) ? 1.f : 0.f);
        *(__nv_bfloat162*)(op + j) = p2;
    }
}

// ---------------------------------------------------------------------------
// Gather temporal proj spikes: dst[((n*B+b)*H+h)*320 + t*32 + e]
// ---------------------------------------------------------------------------
__global__ void __launch_bounds__(256) k_gather_temporal() {
    const int bx = blockIdx.x;
    const int which = bx / 5760;
    const int r = bx - which * 5760;
    const int ntile = r % 12;
    const int tbh = r / 12;
    const int tb = tbh / 12;
    const int h = tbh - tb * 12;
    const int t = tb / BB;
    const int b = tb - t * BB;

    const float* srcbase = (which == 0) ? g_pq : (which == 1) ? g_pk : g_pv;
    float* dst = (which == 0) ? g_tq : (which == 1) ? g_tk : g_tv;
    const float* src = srcbase + (size_t)tb * CN + (size_t)h * 32 * NN + ntile * 32;

    __shared__ float tile[32][33];
    const int tid = threadIdx.x;
#pragma unroll
    for (int i = 0; i < 4; ++i) {
        int idx = tid + i * 256;
        int ee = idx >> 5, nn = idx & 31;
        tile[ee][nn] = src[(size_t)ee * NN + nn];
    }
    __syncthreads();
#pragma unroll
    for (int i = 0; i < 4; ++i) {
        int idx = tid + i * 256;
        int nn = idx >> 5, ee = idx & 31;
        int n = ntile * 32 + nn;
        dst[((size_t)(n * BB + b) * HH + h) * 320 + t * 32 + ee] = tile[ee][nn];
    }
}

// ---------------------------------------------------------------------------
// Temporal attention per (n,b,h); bf16 spikes to g_osT via torch reshape
// shuffle flat = h*320+t*32+dd -> (t',c').
// ---------------------------------------------------------------------------
__global__ void __launch_bounds__(256) k_temporal_attn() {
    __shared__ float qs[8][321];
    __shared__ float ks2[8][321];
    __shared__ float vs2[8][321];
    __shared__ float at[8][112];

    const int wid = threadIdx.x >> 5;
    const int lane = threadIdx.x & 31;
    const int nbh = blockIdx.x * 8 + wid;
    const int h = nbh % HH;
    const int nb = nbh / HH;
    const int b = nb % BB;
    const int n = nb / BB;

    const float* qg = g_tq + (size_t)nbh * 320;
    const float* kg = g_tk + (size_t)nbh * 320;
    const float* vg = g_tv + (size_t)nbh * 320;

#pragma unroll
    for (int i = 0; i < TT; ++i) {
        qs[wid][lane * TT + i] = qg[i * 32 + lane];
        ks2[wid][lane * TT + i] = kg[i * 32 + lane];
        vs2[wid][i * 32 + lane] = vg[i * 32 + lane];
    }
    __syncwarp();

    for (int ii = lane; ii < 100; ii += 32) {
        int t = ii / 10, s = ii - t * 10;
        float acc = 0.f;
#pragma unroll
        for (int ee = 0; ee < 32; ++ee)
            acc = fmaf(qs[wid][ee * TT + t], ks2[wid][ee * TT + s], acc);
        at[wid][ii] = acc;
    }
    __syncwarp();

#pragma unroll
    for (int t = 0; t < TT; ++t) {
        float acc = 0.f;
#pragma unroll
        for (int s = 0; s < TT; ++s)
            acc = fmaf(at[wid][t * 10 + s], vs2[wid][s * 32 + lane], acc);
        float sp = (acc >= 8.0f) ? 1.0f : 0.0f;
        int flat = h * 320 + t * 32 + lane;
        int tp = flat / 384;
        int cp = flat - tp * 384;
        g_osT[(size_t)(tp * BB + b) * CN + (size_t)n * CC + cp] = __float2bfloat16(sp);
    }
}

// ---------------------------------------------------------------------------
// reductions + outer product
// ---------------------------------------------------------------------------
__global__ void __launch_bounds__(256) k_reduce_b() {
    const int i = blockIdx.x * 256 + threadIdx.x;
    float s = 0.f;
#pragma unroll
    for (int t = 0; t < TT; ++t) s += g_a[(size_t)t * BCN + i];
    g_bred[i] = s / (float)TT;
}

__global__ void __launch_bounds__(256) k_outer(float* __restrict__ out) { // 5760 blocks
    const int i = blockIdx.x * 256 + threadIdx.x;
    const int e = i * 4;
    const int n = e % NN;
    const int rest = e / NN;
    const int c = rest % CC;
    const int tb = rest / CC;
    const int b = tb % BB;
    const float a = g_ared[tb * CC + c] * (1.0f / 384.0f);
    const float* bp = &g_bred[((size_t)b * CC + c) * NN + n];
    float4 w;
    w.x = a * bp[0]; w.y = a * bp[1]; w.z = a * bp[2]; w.w = a * bp[3];
    *(float4*)(out + e) = w;
}

// ---------------------------------------------------------------------------
extern "C" void kernel_launch(void* const* d_in, const int* in_sizes, int n_in,
                              void* d_out, int out_size)
{
    const float* x   = (const float*)d_in[0];
    const float* y   = (const float*)d_in[1];
    const float* sW  = (const float*)d_in[2];
    const float* sg  = (const float*)d_in[3];
    const float* sb  = (const float*)d_in[4];
    const float* tW  = (const float*)d_in[5];
    const float* tg  = (const float*)d_in[6];
    const float* tbn = (const float*)d_in[7];
    float* out = (float*)d_out;

    cudaFuncSetAttribute(k_qkv_all, cudaFuncAttributeMaxDynamicSharedMemorySize, SMEM_QKV);
    cudaFuncSetAttribute(k_final_all, cudaFuncAttributeMaxDynamicSharedMemorySize, SMEM_FIN);

    // precompute splits
    k_split_w<<<4608, 256>>>(sW, tW);
    k_split_xy<<<11520, 256>>>(x, y);
    k_zero_ared<<<60, 256>>>();

    // all 6 qkv projections (both paths), persistent grid (2 CTAs/SM x 148)
    k_qkv_all<<<296, 256, SMEM_QKV>>>(sg, sb, tg, tbn);

    // ---- spatial path ----
    k_kvM<<<480, 256>>>();
    k_qM<<<480 * 3, 256>>>();

    // ---- temporal path (before finals so finals merge) ----
    k_gather_temporal<<<3 * 5760, 256>>>();
    k_temporal_attn<<<(NN * BB * HH) / 8, 256>>>();

    // merged final convs (spatial fused row-mean + temporal)
    k_final_all<<<dim3(3, 3, 80), 256, SMEM_FIN>>>(sg, sb, tg, tbn);

    k_reduce_b<<<BCN / 256, 256>>>();

    // ---- combine ----
    k_outer<<<TBCN / 1024, 256>>>(out);
}

// round 9
// speedup vs baseline: 1.8009x; 1.0411x over previous
#include <cuda_runtime.h>
#include <cuda_bf16.h>
#include <cstdint>

// ---------------------------------------------------------------------------
// Spikformer spatial+temporal SSA — bf16 mma.sync, cp.async double-buffered,
// register-cached B fragments, work-queue persistent GEMMs.
//  - LIF outputs exactly binary; thresholds exact (>=2 conv, >=8 attention).
//  - fp32 = 3x bf16 split (exact); qkv GEMM = 6 bf16 term-pairs (fp32-exact),
//    final conv (binary B) = 3 term-pairs.
// ---------------------------------------------------------------------------

#define TT 10
#define BB 4
#define CC 384
#define NN 384
#define HH 12
#define CN (CC * NN)             // 147456
#define TBCN (TT * BB * CC * NN) // 5898240
#define BCN (BB * CC * NN)       // 589824

// scratch
__device__ __align__(128) float g_q[TBCN];   // spatial q spikes [tb][c][n]
__device__ __align__(128) float g_k[TBCN];
__device__ __align__(128) float g_v[TBCN];
__device__ __align__(128) float g_pq[TBCN];  // temporal proj spikes [tb][c][n]
__device__ __align__(128) float g_pk[TBCN];
__device__ __align__(128) float g_pv[TBCN];
__device__ __align__(128) float g_a[TBCN];   // temporal final spikes
__device__ __align__(128) float g_tq[TBCN];  // temporal gathered [(n*B+b)*H+h][t*32+e]
__device__ __align__(128) float g_tk[TBCN];
__device__ __align__(128) float g_tv[TBCN];
__device__ __align__(128) float g_M[480 * 1024];                // spatial k^T v
__device__ __align__(128) __nv_bfloat16 g_osT[TBCN];            // spatial attn spikes [tb][n][c]
__device__ __align__(128) __nv_bfloat16 g_osT2[TBCN];           // temporal attn spikes [tb][n][c]
__device__ __align__(128) __nv_bfloat16 g_Wc[8 * 3 * CN];       // [mat][comp][o][c]
__device__ __align__(128) __nv_bfloat16 g_XT[2 * 3 * 40 * CN];  // [sel][comp][tb][n][c]
__device__ float g_ared[TT * BB * CC]; // raw row sums (spatial)
__device__ float g_bred[BCN];
__device__ unsigned g_ctr_qkv;
__device__ unsigned g_ctr_fin;

__device__ __forceinline__ uint32_t smem_u32(const void* p) {
    uint32_t a;
    asm("{ .reg .u64 t; cvta.to.shared.u64 t, %1; cvt.u32.u64 %0, t; }"
        : "=r"(a) : "l"(p));
    return a;
}

__device__ __forceinline__ void ldsm_x4(uint32_t addr, uint32_t& r0, uint32_t& r1,
                                        uint32_t& r2, uint32_t& r3) {
    asm volatile("ldmatrix.sync.aligned.m8n8.x4.shared.b16 {%0,%1,%2,%3}, [%4];"
                 : "=r"(r0), "=r"(r1), "=r"(r2), "=r"(r3) : "r"(addr));
}

__device__ __forceinline__ void mma_bf16(float* c, const uint32_t* a,
                                         uint32_t b0, uint32_t b1) {
    asm volatile(
        "mma.sync.aligned.m16n8k16.row.col.f32.bf16.bf16.f32 "
        "{%0,%1,%2,%3}, {%4,%5,%6,%7}, {%8,%9}, {%0,%1,%2,%3};"
        : "+f"(c[0]), "+f"(c[1]), "+f"(c[2]), "+f"(c[3])
        : "r"(a[0]), "r"(a[1]), "r"(a[2]), "r"(a[3]), "r"(b0), "r"(b1));
}

__device__ __forceinline__ uint32_t swz64(uint32_t off) {
    return off ^ ((off >> 3) & 0x30);
}

__device__ __forceinline__ void cp16(uint32_t dst, const void* src) {
    asm volatile("cp.async.cg.shared.global [%0], [%1], 16;" :: "r"(dst), "l"(src));
}

#define SMEM_QKV 99328
#define SMEM_FIN 66560

// ---------------------------------------------------------------------------
// fp32 -> 3x bf16 exact split precompute + init (counters, ared)
// ---------------------------------------------------------------------------
__device__ __forceinline__ void split3(float x, __nv_bfloat16& a, __nv_bfloat16& b,
                                       __nv_bfloat16& c) {
    a = __float2bfloat16(x);
    float r = x - __bfloat162float(a);
    b = __float2bfloat16(r);
    float r2 = r - __bfloat162float(b);
    c = __float2bfloat16(r2);
}

__global__ void __launch_bounds__(256) k_init() {
    int i = blockIdx.x * 256 + threadIdx.x;
    if (i < TT * BB * CC) g_ared[i] = 0.0f;
    if (i == 0) { g_ctr_qkv = 0u; g_ctr_fin = 0u; }
}

__global__ void __launch_bounds__(256) k_split_w(const float* __restrict__ sW,
                                                 const float* __restrict__ tW) {
    int i = blockIdx.x * 256 + threadIdx.x;
    float w = (i < 4 * CN) ? sW[i] : tW[i - 4 * CN];
    int m = i / CN, e = i - m * CN;
    __nv_bfloat16 c1, c2, c3;
    split3(w, c1, c2, c3);
    size_t base = (size_t)m * 3 * CN + e;
    g_Wc[base] = c1;
    g_Wc[base + CN] = c2;
    g_Wc[base + 2 * CN] = c3;
}

__global__ void __launch_bounds__(256) k_split_xy(const float* __restrict__ x,
                                                  const float* __restrict__ y) {
    __shared__ float t[32][33];
    int bx = blockIdx.x;
    int sel = bx / 5760;
    int r = bx - sel * 5760;
    int tb = r / 144, tl = r - tb * 144;
    int ct = tl / 12, nt = tl - ct * 12;
    const float* src = (sel ? y : x) + (size_t)tb * CN + (size_t)(ct * 32) * NN + nt * 32;
    int tid = threadIdx.x;
#pragma unroll
    for (int i = 0; i < 4; ++i) {
        int idx = tid + i * 256;
        int cl = idx >> 5, nl = idx & 31;
        t[cl][nl] = src[(size_t)cl * NN + nl];
    }
    __syncthreads();
#pragma unroll
    for (int i = 0; i < 4; ++i) {
        int idx = tid + i * 256;
        int nl = idx >> 5, cl = idx & 31;
        __nv_bfloat16 c1, c2, c3;
        split3(t[cl][nl], c1, c2, c3);
        size_t base = ((size_t)(sel * 3) * 40 + tb) * CN + (size_t)(nt * 32 + nl) * CC + ct * 32 + cl;
        g_XT[base] = c1;
        g_XT[base + (size_t)40 * CN] = c2;
        g_XT[base + (size_t)80 * CN] = c3;
    }
}

// ---------------------------------------------------------------------------
// cp.async double-buffered tensor-core GEMM tile, register-cached B frags,
// single __syncthreads per stage.
// D[128,128] = sum_pairs A_pa[128,384] * B_pb[128,384]^T  (both K-major)
// 12 stages of K=32, SMEM tiles 128x32 bf16 with SW64 swizzle.
// suma: fuse row-sum into epilogue via atomics (Ob indexed by channel row).
// ---------------------------------------------------------------------------
template <int NBC>
__device__ __forceinline__ void tc_gemm_body(
    const __nv_bfloat16* __restrict__ A0,
    const __nv_bfloat16* __restrict__ B0, size_t bcs,
    const float* __restrict__ gs, const float* __restrict__ bs,
    float* __restrict__ Ob, int o0, int n0, bool suma)
{
    constexpr int NC = 3 + NBC;
    constexpr uint32_t STAGE = NC * 8192u;
    extern __shared__ char smem_raw[];
    const uint32_t ab = (smem_u32(smem_raw) + 1023u) & ~1023u;
    const int tid = threadIdx.x;
    const int lane = tid & 31;
    const int wid = tid >> 5;
    const int wm = (wid >> 2) * 64;
    const int wn = (wid & 3) * 32;

    float acc[4][4][4];
#pragma unroll
    for (int mi = 0; mi < 4; ++mi)
#pragma unroll
        for (int ni = 0; ni < 4; ++ni)
#pragma unroll
            for (int r = 0; r < 4; ++r) acc[mi][ni][r] = 0.0f;

    const int a_row_l = lane & 15;
    const int a_ch = (lane >> 4) << 4;
    const int b_row_l = ((lane >> 4) & 1) * 8 + (lane & 7);
    const int b_ch = ((lane >> 3) & 1) << 4;

    auto load_stage = [&](int s, uint32_t buf) {
#pragma unroll
        for (int i = 0; i < NC * 2; ++i) {
            int idx = tid + i * 256;
            int comp = idx >> 9;
            int rem = idx & 511;
            int row = rem >> 2, ch = rem & 3;
            const __nv_bfloat16* g =
                (comp < 3) ? (A0 + (size_t)comp * CN) : (B0 + (size_t)(comp - 3) * bcs);
            g += (size_t)row * CC + s * 32 + ch * 8;
            uint32_t d = buf + comp * 8192 + swz64((uint32_t)(row * 64 + ch * 16));
            cp16(d, g);
        }
        asm volatile("cp.async.commit_group;" ::: "memory");
    };

    auto load_bf = [&](uint32_t base, int ks, uint32_t bf[4][2]) {
#pragma unroll
        for (int bi = 0; bi < 2; ++bi) {
            int row = wn + bi * 16 + b_row_l;
            uint32_t off = (uint32_t)(row * 64 + ks * 32 + b_ch);
            uint32_t r0, r1, r2, r3;
            ldsm_x4(base + swz64(off), r0, r1, r2, r3);
            bf[bi * 2][0] = r0; bf[bi * 2][1] = r1;
            bf[bi * 2 + 1][0] = r2; bf[bi * 2 + 1][1] = r3;
        }
    };
    auto load_af = [&](uint32_t base, int ks, int mi, uint32_t* af) {
        int row = wm + mi * 16 + a_row_l;
        uint32_t off = (uint32_t)(row * 64 + ks * 32 + a_ch);
        ldsm_x4(base + swz64(off), af[0], af[1], af[2], af[3]);
    };

    load_stage(0, ab);
    for (int s = 0; s < 12; ++s) {
        const uint32_t cur = ab + (uint32_t)(s & 1) * STAGE;
        asm volatile("cp.async.wait_group 0;" ::: "memory"); // stage s arrived
        __syncthreads();  // also: all warps finished compute(s-1) -> other buf free
        if (s < 11) load_stage(s + 1, ab + (uint32_t)((s + 1) & 1) * STAGE);

#pragma unroll
        for (int ks = 0; ks < 2; ++ks) {
            uint32_t b0[4][2];
            load_bf(cur + 3 * 8192, ks, b0); // pb=0, cached (used by all pa)
#pragma unroll
            for (int pa = 0; pa < 3; ++pa) {
                uint32_t afr[4][4];
#pragma unroll
                for (int mi = 0; mi < 4; ++mi) load_af(cur + pa * 8192, ks, mi, afr[mi]);
#pragma unroll
                for (int mi = 0; mi < 4; ++mi)
#pragma unroll
                    for (int ni = 0; ni < 4; ++ni)
                        mma_bf16(acc[mi][ni], afr[mi], b0[ni][0], b0[ni][1]);
                if (NBC == 3) {
                    if (pa < 2) { // pb=1 (pairs (0,1),(1,1))
                        uint32_t bt[4][2];
                        load_bf(cur + 4 * 8192, ks, bt);
#pragma unroll
                        for (int mi = 0; mi < 4; ++mi)
#pragma unroll
                            for (int ni = 0; ni < 4; ++ni)
                                mma_bf16(acc[mi][ni], afr[mi], bt[ni][0], bt[ni][1]);
                    }
                    if (pa == 0) { // pb=2 (pair (0,2))
                        uint32_t bt[4][2];
                        load_bf(cur + 5 * 8192, ks, bt);
#pragma unroll
                        for (int mi = 0; mi < 4; ++mi)
#pragma unroll
                            for (int ni = 0; ni < 4; ++ni)
                                mma_bf16(acc[mi][ni], afr[mi], bt[ni][0], bt[ni][1]);
                    }
                }
            }
        }
    }

    // epilogue: BN + spike. row = channel index (always in [0,384)).
#pragma unroll
    for (int mi = 0; mi < 4; ++mi) {
#pragma unroll
        for (int half = 0; half < 2; ++half) {
            const int row = o0 + wm + mi * 16 + half * 8 + (lane >> 2);
            const float gv = gs[row];
            const float bv = bs[row];
            float vals[8];
#pragma unroll
            for (int ni = 0; ni < 4; ++ni) {
                vals[ni * 2 + 0] = (fmaf(acc[mi][ni][half * 2 + 0], gv, bv) >= 2.0f) ? 1.f : 0.f;
                vals[ni * 2 + 1] = (fmaf(acc[mi][ni][half * 2 + 1], gv, bv) >= 2.0f) ? 1.f : 0.f;
            }
            if (suma) {
                float sum = 0.f;
#pragma unroll
                for (int j = 0; j < 8; ++j) sum += vals[j];
                sum += __shfl_xor_sync(0xffffffffu, sum, 1);
                sum += __shfl_xor_sync(0xffffffffu, sum, 2);
                if ((lane & 3) == 0) atomicAdd(&Ob[row], sum);
            } else {
                float* dst = Ob + (size_t)row * NN + n0 + wn + (lane & 3) * 2;
#pragma unroll
                for (int ni = 0; ni < 4; ++ni) {
                    float2 w;
                    w.x = vals[ni * 2 + 0];
                    w.y = vals[ni * 2 + 1];
                    *(float2*)(dst + ni * 8) = w;
                }
            }
        }
    }
}

// Work-queue persistent qkv for BOTH paths: 2160 tiles.
__global__ void __launch_bounds__(256, 2) k_qkv_all(
    const float* __restrict__ sg, const float* __restrict__ sb,
    const float* __restrict__ tg, const float* __restrict__ tb_)
{
    __shared__ unsigned s_tile;
    for (;;) {
        if (threadIdx.x == 0) s_tile = atomicAdd(&g_ctr_qkv, 1u);
        __syncthreads();
        unsigned tile = s_tile;
        if (tile >= 2160u) break;
        // (s_tile rewrite next iter is ordered after all reads by the GEMM's
        //  internal stage-0 __syncthreads.)
        int nx = tile % 3;
        int rest = tile / 3;
        int my = rest % 3;
        int z = rest / 3;
        int pj = z / 40, tb = z - pj * 40;
        int path = pj / 3, j = pj - path * 3;
        int o0 = my * 128, n0 = nx * 128;
        const __nv_bfloat16* A0 = g_Wc + (size_t)((path * 4 + j) * 3) * CN + (size_t)o0 * CC;
        int sel = (j == 0) ? 0 : 1;
        const __nv_bfloat16* B0 = g_XT + ((size_t)(sel * 3) * 40 + tb) * CN + (size_t)n0 * CC;
        float* Ob;
        if (path == 0) Ob = (j == 0) ? g_q : (j == 1) ? g_k : g_v;
        else           Ob = (j == 0) ? g_pq : (j == 1) ? g_pk : g_pv;
        const float* gs = (path == 0) ? sg : tg;
        const float* bs = (path == 0) ? sb : tb_;
        tc_gemm_body<3>(A0, B0, (size_t)40 * CN, gs + j * CC, bs + j * CC,
                        Ob + (size_t)tb * CN, o0, n0, false);
        __syncthreads();
    }
}

// Work-queue persistent merged final convs: 720 tiles.
// tile -> (nx, my, z); z<40: spatial (fused row-mean, reads g_osT), else
// temporal (reads g_osT2).
__global__ void __launch_bounds__(256, 2) k_final_all(
    const float* __restrict__ sg, const float* __restrict__ sb,
    const float* __restrict__ tg, const float* __restrict__ tb_)
{
    __shared__ unsigned s_tile;
    for (;;) {
        if (threadIdx.x == 0) s_tile = atomicAdd(&g_ctr_fin, 1u);
        __syncthreads();
        unsigned tile = s_tile;
        if (tile >= 720u) break;
        int nx = tile % 3;
        int rest = tile / 3;
        int my = rest % 3;
        int z = rest / 3;
        int path = z / 40, tb = z - path * 40;
        int o0 = my * 128, n0 = nx * 128;
        const __nv_bfloat16* A0 = g_Wc + (size_t)((path * 4 + 3) * 3) * CN + (size_t)o0 * CC;
        const __nv_bfloat16* B0 =
            ((path == 0) ? g_osT : g_osT2) + (size_t)tb * CN + (size_t)n0 * CC;
        const float* gs = (path == 0) ? sg : tg;
        const float* bs = (path == 0) ? sb : tb_;
        float* Ob = (path == 0) ? (g_ared + (size_t)tb * CC) : (g_a + (size_t)tb * CN);
        tc_gemm_body<1>(A0, B0, 0, gs + 3 * CC, bs + 3 * CC, Ob, o0, n0, path == 0);
        __syncthreads();
    }
}

// ---------------------------------------------------------------------------
// Spatial attention: phase 1 -> M = k^T v per (t,b,h), stored to g_M.
// ---------------------------------------------------------------------------
__global__ void __launch_bounds__(256) k_kvM() {
    __shared__ float ks[64][33];
    __shared__ float vs[64][33];

    const int blk = blockIdx.x;
    const int tb = blk / HH;
    const int h = blk - tb * HH;
    const size_t base = (size_t)tb * CN + (size_t)h * 32 * NN;
    const float* kb = g_k + base;
    const float* vb = g_v + base;
    const int tid = threadIdx.x;

    const int e = tid >> 3;
    const int dd0 = (tid & 7) << 2;
    float mc0 = 0.f, mc1 = 0.f, mc2 = 0.f, mc3 = 0.f;
    for (int m0 = 0; m0 < NN; m0 += 64) {
#pragma unroll
        for (int i = 0; i < 8; ++i) {
            int idx = tid + i * 256;
            int ee = idx >> 6, mm = idx & 63;
            ks[mm][ee] = kb[(size_t)ee * NN + m0 + mm];
            vs[mm][ee] = vb[(size_t)ee * NN + m0 + mm];
        }
        __syncthreads();
#pragma unroll 8
        for (int mm = 0; mm < 64; ++mm) {
            float kv = ks[mm][e];
            mc0 = fmaf(kv, vs[mm][dd0 + 0], mc0);
            mc1 = fmaf(kv, vs[mm][dd0 + 1], mc1);
            mc2 = fmaf(kv, vs[mm][dd0 + 2], mc2);
            mc3 = fmaf(kv, vs[mm][dd0 + 3], mc3);
        }
        __syncthreads();
    }
    float* Mp = g_M + (size_t)blk * 1024 + e * 32 + dd0;
    Mp[0] = mc0; Mp[1] = mc1; Mp[2] = mc2; Mp[3] = mc3;
}

// Phase 2: o = q M, spike >= 8, write transposed bf16 into g_osT[tb][n][c].
__global__ void __launch_bounds__(256) k_qM() {
    __shared__ float Ms[32][32];
    const int blk = blockIdx.x;
    const int tbh = blk / 3;
    const int nt = blk - tbh * 3;
    const int tb = tbh / HH;
    const int h = tbh - tb * HH;
    const int tid = threadIdx.x;

#pragma unroll
    for (int i = 0; i < 4; ++i) {
        int idx = tid + i * 256;
        Ms[idx >> 5][idx & 31] = g_M[(size_t)tbh * 1024 + idx];
    }
    __syncthreads();

    const int n = nt * 128 + (tid & 127);
    const int d0 = (tid >> 7) * 16;
    const float* qb = g_q + (size_t)tb * CN + (size_t)h * 32 * NN + n;

    float acc[16];
#pragma unroll
    for (int j = 0; j < 16; ++j) acc[j] = 0.f;
#pragma unroll
    for (int e = 0; e < 32; ++e) {
        float qv = qb[(size_t)e * NN];
#pragma unroll
        for (int j = 0; j < 16; ++j) acc[j] = fmaf(qv, Ms[e][d0 + j], acc[j]);
    }
    __nv_bfloat16* op = g_osT + (size_t)tb * CN + (size_t)n * CC + h * 32 + d0;
#pragma unroll
    for (int j = 0; j < 16; j += 2) {
        __nv_bfloat162 p2;
        p2.x = __float2bfloat16((acc[j] >= 8.0f) ? 1.f : 0.f);
        p2.y = __float2bfloat16((acc[j + 1] >= 8.0f) ? 1.f : 0.f);
        *(__nv_bfloat162*)(op + j) = p2;
    }
}

// ---------------------------------------------------------------------------
// Gather temporal proj spikes: dst[((n*B+b)*H+h)*320 + t*32 + e]
// ---------------------------------------------------------------------------
__global__ void __launch_bounds__(256) k_gather_temporal() {
    const int bx = blockIdx.x;
    const int which = bx / 5760;
    const int r = bx - which * 5760;
    const int ntile = r % 12;
    const int tbh = r / 12;
    const int tb = tbh / 12;
    const int h = tbh - tb * 12;
    const int t = tb / BB;
    const int b = tb - t * BB;

    const float* srcbase = (which == 0) ? g_pq : (which == 1) ? g_pk : g_pv;
    float* dst = (which == 0) ? g_tq : (which == 1) ? g_tk : g_tv;
    const float* src = srcbase + (size_t)tb * CN + (size_t)h * 32 * NN + ntile * 32;

    __shared__ float tile[32][33];
    const int tid = threadIdx.x;
#pragma unroll
    for (int i = 0; i < 4; ++i) {
        int idx = tid + i * 256;
        int ee = idx >> 5, nn = idx & 31;
        tile[ee][nn] = src[(size_t)ee * NN + nn];
    }
    __syncthreads();
#pragma unroll
    for (int i = 0; i < 4; ++i) {
        int idx = tid + i * 256;
        int nn = idx >> 5, ee = idx & 31;
        int n = ntile * 32 + nn;
        dst[((size_t)(n * BB + b) * HH + h) * 320 + t * 32 + ee] = tile[ee][nn];
    }
}

// ---------------------------------------------------------------------------
// Temporal attention per (n,b,h); bf16 spikes to g_osT2 via torch reshape
// shuffle flat = h*320+t*32+dd -> (t',c').
// ---------------------------------------------------------------------------
__global__ void __launch_bounds__(256) k_temporal_attn() {
    __shared__ float qs[8][321];
    __shared__ float ks2[8][321];
    __shared__ float vs2[8][321];
    __shared__ float at[8][112];

    const int wid = threadIdx.x >> 5;
    const int lane = threadIdx.x & 31;
    const int nbh = blockIdx.x * 8 + wid;
    const int h = nbh % HH;
    const int nb = nbh / HH;
    const int b = nb % BB;
    const int n = nb / BB;

    const float* qg = g_tq + (size_t)nbh * 320;
    const float* kg = g_tk + (size_t)nbh * 320;
    const float* vg = g_tv + (size_t)nbh * 320;

#pragma unroll
    for (int i = 0; i < TT; ++i) {
        qs[wid][lane * TT + i] = qg[i * 32 + lane];
        ks2[wid][lane * TT + i] = kg[i * 32 + lane];
        vs2[wid][i * 32 + lane] = vg[i * 32 + lane];
    }
    __syncwarp();

    for (int ii = lane; ii < 100; ii += 32) {
        int t = ii / 10, s = ii - t * 10;
        float acc = 0.f;
#pragma unroll
        for (int ee = 0; ee < 32; ++ee)
            acc = fmaf(qs[wid][ee * TT + t], ks2[wid][ee * TT + s], acc);
        at[wid][ii] = acc;
    }
    __syncwarp();

#pragma unroll
    for (int t = 0; t < TT; ++t) {
        float acc = 0.f;
#pragma unroll
        for (int s = 0; s < TT; ++s)
            acc = fmaf(at[wid][t * 10 + s], vs2[wid][s * 32 + lane], acc);
        float sp = (acc >= 8.0f) ? 1.0f : 0.0f;
        int flat = h * 320 + t * 32 + lane;
        int tp = flat / 384;
        int cp = flat - tp * 384;
        g_osT2[(size_t)(tp * BB + b) * CN + (size_t)n * CC + cp] = __float2bfloat16(sp);
    }
}

// ---------------------------------------------------------------------------
// reductions + outer product
// ---------------------------------------------------------------------------
__global__ void __launch_bounds__(256) k_reduce_b() {
    const int i = blockIdx.x * 256 + threadIdx.x;
    float s = 0.f;
#pragma unroll
    for (int t = 0; t < TT; ++t) s += g_a[(size_t)t * BCN + i];
    g_bred[i] = s / (float)TT;
}

__global__ void __launch_bounds__(256) k_outer(float* __restrict__ out) { // 5760 blocks
    const int i = blockIdx.x * 256 + threadIdx.x;
    const int e = i * 4;
    const int n = e % NN;
    const int rest = e / NN;
    const int c = rest % CC;
    const int tb = rest / CC;
    const int b = tb % BB;
    const float a = g_ared[tb * CC + c] * (1.0f / 384.0f);
    const float* bp = &g_bred[((size_t)b * CC + c) * NN + n];
    float4 w;
    w.x = a * bp[0]; w.y = a * bp[1]; w.z = a * bp[2]; w.w = a * bp[3];
    *(float4*)(out + e) = w;
}

// ---------------------------------------------------------------------------
extern "C" void kernel_launch(void* const* d_in, const int* in_sizes, int n_in,
                              void* d_out, int out_size)
{
    const float* x   = (const float*)d_in[0];
    const float* y   = (const float*)d_in[1];
    const float* sW  = (const float*)d_in[2];
    const float* sg  = (const float*)d_in[3];
    const float* sb  = (const float*)d_in[4];
    const float* tW  = (const float*)d_in[5];
    const float* tg  = (const float*)d_in[6];
    const float* tbn = (const float*)d_in[7];
    float* out = (float*)d_out;

    cudaFuncSetAttribute(k_qkv_all, cudaFuncAttributeMaxDynamicSharedMemorySize, SMEM_QKV);
    cudaFuncSetAttribute(k_final_all, cudaFuncAttributeMaxDynamicSharedMemorySize, SMEM_FIN);

    // init + precompute splits
    k_init<<<60, 256>>>();
    k_split_w<<<4608, 256>>>(sW, tW);
    k_split_xy<<<11520, 256>>>(x, y);

    // all 6 qkv projections (both paths), work-queue persistent
    k_qkv_all<<<296, 256, SMEM_QKV>>>(sg, sb, tg, tbn);

    // ---- spatial path ----
    k_kvM<<<480, 256>>>();
    k_qM<<<480 * 3, 256>>>();

    // ---- temporal path ----
    k_gather_temporal<<<3 * 5760, 256>>>();
    k_temporal_attn<<<(NN * BB * HH) / 8, 256>>>();

    // merged final convs (spatial fused row-mean + temporal), work-queue
    k_final_all<<<296, 256, SMEM_FIN>>>(sg, sb, tg, tbn);

    k_reduce_b<<<BCN / 256, 256>>>();

    // ---- combine ----
    k_outer<<<TBCN / 1024, 256>>>(out);
}

// round 10
// speedup vs baseline: 1.8601x; 1.0329x over previous
#include <cuda_runtime.h>
#include <cuda_bf16.h>
#include <cstdint>

// ---------------------------------------------------------------------------
// Spikformer spatial+temporal SSA — bf16 mma.sync, cp.async double-buffered,
// register-cached B fragments, work-queue persistent GEMMs, bf16 spike
// storage everywhere (spikes are exactly binary -> bf16 exact).
// ---------------------------------------------------------------------------

#define TT 10
#define BB 4
#define CC 384
#define NN 384
#define HH 12
#define CN (CC * NN)             // 147456
#define TBCN (TT * BB * CC * NN) // 5898240
#define BCN (BB * CC * NN)       // 589824

// scratch (spike tensors in bf16 — binary values, exact)
__device__ __align__(128) __nv_bfloat16 g_q[TBCN];   // spatial q spikes [tb][c][n]
__device__ __align__(128) __nv_bfloat16 g_k[TBCN];
__device__ __align__(128) __nv_bfloat16 g_v[TBCN];
__device__ __align__(128) __nv_bfloat16 g_pq[TBCN];  // temporal proj spikes [tb][c][n]
__device__ __align__(128) __nv_bfloat16 g_pk[TBCN];
__device__ __align__(128) __nv_bfloat16 g_pv[TBCN];
__device__ __align__(128) __nv_bfloat16 g_a[TBCN];   // temporal final spikes
__device__ __align__(128) __nv_bfloat16 g_tq[TBCN];  // gathered [(n*B+b)*H+h][t*32+e]
__device__ __align__(128) __nv_bfloat16 g_tk[TBCN];
__device__ __align__(128) __nv_bfloat16 g_tv[TBCN];
__device__ __align__(128) float g_M[480 * 1024];                // spatial k^T v
__device__ __align__(128) __nv_bfloat16 g_osT[TBCN];            // spatial attn spikes [tb][n][c]
__device__ __align__(128) __nv_bfloat16 g_osT2[TBCN];           // temporal attn spikes [tb][n][c]
__device__ __align__(128) __nv_bfloat16 g_Wc[8 * 3 * CN];       // [mat][comp][o][c]
__device__ __align__(128) __nv_bfloat16 g_XT[2 * 3 * 40 * CN];  // [sel][comp][tb][n][c]
__device__ float g_ared[TT * BB * CC]; // raw row sums (spatial)
__device__ float g_bred[BCN];
__device__ unsigned g_ctr_qkv;
__device__ unsigned g_ctr_fin;

__device__ __forceinline__ uint32_t smem_u32(const void* p) {
    uint32_t a;
    asm("{ .reg .u64 t; cvta.to.shared.u64 t, %1; cvt.u32.u64 %0, t; }"
        : "=r"(a) : "l"(p));
    return a;
}

__device__ __forceinline__ void ldsm_x4(uint32_t addr, uint32_t& r0, uint32_t& r1,
                                        uint32_t& r2, uint32_t& r3) {
    asm volatile("ldmatrix.sync.aligned.m8n8.x4.shared.b16 {%0,%1,%2,%3}, [%4];"
                 : "=r"(r0), "=r"(r1), "=r"(r2), "=r"(r3) : "r"(addr));
}

__device__ __forceinline__ void mma_bf16(float* c, const uint32_t* a,
                                         uint32_t b0, uint32_t b1) {
    asm volatile(
        "mma.sync.aligned.m16n8k16.row.col.f32.bf16.bf16.f32 "
        "{%0,%1,%2,%3}, {%4,%5,%6,%7}, {%8,%9}, {%0,%1,%2,%3};"
        : "+f"(c[0]), "+f"(c[1]), "+f"(c[2]), "+f"(c[3])
        : "r"(a[0]), "r"(a[1]), "r"(a[2]), "r"(a[3]), "r"(b0), "r"(b1));
}

__device__ __forceinline__ uint32_t swz64(uint32_t off) {
    return off ^ ((off >> 3) & 0x30);
}

__device__ __forceinline__ void cp16(uint32_t dst, const void* src) {
    asm volatile("cp.async.cg.shared.global [%0], [%1], 16;" :: "r"(dst), "l"(src));
}

#define SMEM_QKV 99328
#define SMEM_FIN 66560

// ---------------------------------------------------------------------------
// fp32 -> 3x bf16 exact split precompute + init (counters, ared)
// ---------------------------------------------------------------------------
__device__ __forceinline__ void split3(float x, __nv_bfloat16& a, __nv_bfloat16& b,
                                       __nv_bfloat16& c) {
    a = __float2bfloat16(x);
    float r = x - __bfloat162float(a);
    b = __float2bfloat16(r);
    float r2 = r - __bfloat162float(b);
    c = __float2bfloat16(r2);
}

__global__ void __launch_bounds__(256) k_init() {
    int i = blockIdx.x * 256 + threadIdx.x;
    if (i < TT * BB * CC) g_ared[i] = 0.0f;
    if (i == 0) { g_ctr_qkv = 0u; g_ctr_fin = 0u; }
}

__global__ void __launch_bounds__(256) k_split_w(const float* __restrict__ sW,
                                                 const float* __restrict__ tW) {
    int i = blockIdx.x * 256 + threadIdx.x;
    float w = (i < 4 * CN) ? sW[i] : tW[i - 4 * CN];
    int m = i / CN, e = i - m * CN;
    __nv_bfloat16 c1, c2, c3;
    split3(w, c1, c2, c3);
    size_t base = (size_t)m * 3 * CN + e;
    g_Wc[base] = c1;
    g_Wc[base + CN] = c2;
    g_Wc[base + 2 * CN] = c3;
}

__global__ void __launch_bounds__(256) k_split_xy(const float* __restrict__ x,
                                                  const float* __restrict__ y) {
    __shared__ float t[32][33];
    int bx = blockIdx.x;
    int sel = bx / 5760;
    int r = bx - sel * 5760;
    int tb = r / 144, tl = r - tb * 144;
    int ct = tl / 12, nt = tl - ct * 12;
    const float* src = (sel ? y : x) + (size_t)tb * CN + (size_t)(ct * 32) * NN + nt * 32;
    int tid = threadIdx.x;
#pragma unroll
    for (int i = 0; i < 4; ++i) {
        int idx = tid + i * 256;
        int cl = idx >> 5, nl = idx & 31;
        t[cl][nl] = src[(size_t)cl * NN + nl];
    }
    __syncthreads();
#pragma unroll
    for (int i = 0; i < 4; ++i) {
        int idx = tid + i * 256;
        int nl = idx >> 5, cl = idx & 31;
        __nv_bfloat16 c1, c2, c3;
        split3(t[cl][nl], c1, c2, c3);
        size_t base = ((size_t)(sel * 3) * 40 + tb) * CN + (size_t)(nt * 32 + nl) * CC + ct * 32 + cl;
        g_XT[base] = c1;
        g_XT[base + (size_t)40 * CN] = c2;
        g_XT[base + (size_t)80 * CN] = c3;
    }
}

// ---------------------------------------------------------------------------
// cp.async double-buffered tensor-core GEMM tile, register-cached B frags,
// single __syncthreads per stage. Outputs bf16 spikes (or fused row-sum).
// ---------------------------------------------------------------------------
template <int NBC>
__device__ __forceinline__ void tc_gemm_body(
    const __nv_bfloat16* __restrict__ A0,
    const __nv_bfloat16* __restrict__ B0, size_t bcs,
    const float* __restrict__ gs, const float* __restrict__ bs,
    float* __restrict__ obf, __nv_bfloat16* __restrict__ obh,
    int o0, int n0, bool suma)
{
    constexpr int NC = 3 + NBC;
    constexpr uint32_t STAGE = NC * 8192u;
    extern __shared__ char smem_raw[];
    const uint32_t ab = (smem_u32(smem_raw) + 1023u) & ~1023u;
    const int tid = threadIdx.x;
    const int lane = tid & 31;
    const int wid = tid >> 5;
    const int wm = (wid >> 2) * 64;
    const int wn = (wid & 3) * 32;

    float acc[4][4][4];
#pragma unroll
    for (int mi = 0; mi < 4; ++mi)
#pragma unroll
        for (int ni = 0; ni < 4; ++ni)
#pragma unroll
            for (int r = 0; r < 4; ++r) acc[mi][ni][r] = 0.0f;

    const int a_row_l = lane & 15;
    const int a_ch = (lane >> 4) << 4;
    const int b_row_l = ((lane >> 4) & 1) * 8 + (lane & 7);
    const int b_ch = ((lane >> 3) & 1) << 4;

    auto load_stage = [&](int s, uint32_t buf) {
#pragma unroll
        for (int i = 0; i < NC * 2; ++i) {
            int idx = tid + i * 256;
            int comp = idx >> 9;
            int rem = idx & 511;
            int row = rem >> 2, ch = rem & 3;
            const __nv_bfloat16* g =
                (comp < 3) ? (A0 + (size_t)comp * CN) : (B0 + (size_t)(comp - 3) * bcs);
            g += (size_t)row * CC + s * 32 + ch * 8;
            uint32_t d = buf + comp * 8192 + swz64((uint32_t)(row * 64 + ch * 16));
            cp16(d, g);
        }
        asm volatile("cp.async.commit_group;" ::: "memory");
    };

    auto load_bf = [&](uint32_t base, int ks, uint32_t bf[4][2]) {
#pragma unroll
        for (int bi = 0; bi < 2; ++bi) {
            int row = wn + bi * 16 + b_row_l;
            uint32_t off = (uint32_t)(row * 64 + ks * 32 + b_ch);
            uint32_t r0, r1, r2, r3;
            ldsm_x4(base + swz64(off), r0, r1, r2, r3);
            bf[bi * 2][0] = r0; bf[bi * 2][1] = r1;
            bf[bi * 2 + 1][0] = r2; bf[bi * 2 + 1][1] = r3;
        }
    };
    auto load_af = [&](uint32_t base, int ks, int mi, uint32_t* af) {
        int row = wm + mi * 16 + a_row_l;
        uint32_t off = (uint32_t)(row * 64 + ks * 32 + a_ch);
        ldsm_x4(base + swz64(off), af[0], af[1], af[2], af[3]);
    };

    load_stage(0, ab);
    for (int s = 0; s < 12; ++s) {
        const uint32_t cur = ab + (uint32_t)(s & 1) * STAGE;
        asm volatile("cp.async.wait_group 0;" ::: "memory");
        __syncthreads();
        if (s < 11) load_stage(s + 1, ab + (uint32_t)((s + 1) & 1) * STAGE);

#pragma unroll
        for (int ks = 0; ks < 2; ++ks) {
            uint32_t b0[4][2];
            load_bf(cur + 3 * 8192, ks, b0);
#pragma unroll
            for (int pa = 0; pa < 3; ++pa) {
                uint32_t afr[4][4];
#pragma unroll
                for (int mi = 0; mi < 4; ++mi) load_af(cur + pa * 8192, ks, mi, afr[mi]);
#pragma unroll
                for (int mi = 0; mi < 4; ++mi)
#pragma unroll
                    for (int ni = 0; ni < 4; ++ni)
                        mma_bf16(acc[mi][ni], afr[mi], b0[ni][0], b0[ni][1]);
                if (NBC == 3) {
                    if (pa < 2) {
                        uint32_t bt[4][2];
                        load_bf(cur + 4 * 8192, ks, bt);
#pragma unroll
                        for (int mi = 0; mi < 4; ++mi)
#pragma unroll
                            for (int ni = 0; ni < 4; ++ni)
                                mma_bf16(acc[mi][ni], afr[mi], bt[ni][0], bt[ni][1]);
                    }
                    if (pa == 0) {
                        uint32_t bt[4][2];
                        load_bf(cur + 5 * 8192, ks, bt);
#pragma unroll
                        for (int mi = 0; mi < 4; ++mi)
#pragma unroll
                            for (int ni = 0; ni < 4; ++ni)
                                mma_bf16(acc[mi][ni], afr[mi], bt[ni][0], bt[ni][1]);
                    }
                }
            }
        }
    }

    // epilogue: BN + spike. row = channel index (always in [0,384)).
#pragma unroll
    for (int mi = 0; mi < 4; ++mi) {
#pragma unroll
        for (int half = 0; half < 2; ++half) {
            const int row = o0 + wm + mi * 16 + half * 8 + (lane >> 2);
            const float gv = gs[row];
            const float bv = bs[row];
            float vals[8];
#pragma unroll
            for (int ni = 0; ni < 4; ++ni) {
                vals[ni * 2 + 0] = (fmaf(acc[mi][ni][half * 2 + 0], gv, bv) >= 2.0f) ? 1.f : 0.f;
                vals[ni * 2 + 1] = (fmaf(acc[mi][ni][half * 2 + 1], gv, bv) >= 2.0f) ? 1.f : 0.f;
            }
            if (suma) {
                float sum = 0.f;
#pragma unroll
                for (int j = 0; j < 8; ++j) sum += vals[j];
                sum += __shfl_xor_sync(0xffffffffu, sum, 1);
                sum += __shfl_xor_sync(0xffffffffu, sum, 2);
                if ((lane & 3) == 0) atomicAdd(&obf[row], sum);
            } else {
                __nv_bfloat16* dst = obh + (size_t)row * NN + n0 + wn + (lane & 3) * 2;
#pragma unroll
                for (int ni = 0; ni < 4; ++ni) {
                    __nv_bfloat162 w;
                    w.x = __float2bfloat16(vals[ni * 2 + 0]);
                    w.y = __float2bfloat16(vals[ni * 2 + 1]);
                    *(__nv_bfloat162*)(dst + ni * 8) = w;
                }
            }
        }
    }
}

// Work-queue persistent qkv for BOTH paths: 2160 tiles.
__global__ void __launch_bounds__(256, 2) k_qkv_all(
    const float* __restrict__ sg, const float* __restrict__ sb,
    const float* __restrict__ tg, const float* __restrict__ tb_)
{
    __shared__ unsigned s_tile;
    for (;;) {
        if (threadIdx.x == 0) s_tile = atomicAdd(&g_ctr_qkv, 1u);
        __syncthreads();
        unsigned tile = s_tile;
        if (tile >= 2160u) break;
        int nx = tile % 3;
        int rest = tile / 3;
        int my = rest % 3;
        int z = rest / 3;
        int pj = z / 40, tb = z - pj * 40;
        int path = pj / 3, j = pj - path * 3;
        int o0 = my * 128, n0 = nx * 128;
        const __nv_bfloat16* A0 = g_Wc + (size_t)((path * 4 + j) * 3) * CN + (size_t)o0 * CC;
        int sel = (j == 0) ? 0 : 1;
        const __nv_bfloat16* B0 = g_XT + ((size_t)(sel * 3) * 40 + tb) * CN + (size_t)n0 * CC;
        __nv_bfloat16* Ob;
        if (path == 0) Ob = (j == 0) ? g_q : (j == 1) ? g_k : g_v;
        else           Ob = (j == 0) ? g_pq : (j == 1) ? g_pk : g_pv;
        const float* gs = (path == 0) ? sg : tg;
        const float* bs = (path == 0) ? sb : tb_;
        tc_gemm_body<3>(A0, B0, (size_t)40 * CN, gs + j * CC, bs + j * CC,
                        nullptr, Ob + (size_t)tb * CN, o0, n0, false);
        __syncthreads();
    }
}

// Work-queue persistent merged final convs: 720 tiles.
__global__ void __launch_bounds__(256, 2) k_final_all(
    const float* __restrict__ sg, const float* __restrict__ sb,
    const float* __restrict__ tg, const float* __restrict__ tb_)
{
    __shared__ unsigned s_tile;
    for (;;) {
        if (threadIdx.x == 0) s_tile = atomicAdd(&g_ctr_fin, 1u);
        __syncthreads();
        unsigned tile = s_tile;
        if (tile >= 720u) break;
        int nx = tile % 3;
        int rest = tile / 3;
        int my = rest % 3;
        int z = rest / 3;
        int path = z / 40, tb = z - path * 40;
        int o0 = my * 128, n0 = nx * 128;
        const __nv_bfloat16* A0 = g_Wc + (size_t)((path * 4 + 3) * 3) * CN + (size_t)o0 * CC;
        const __nv_bfloat16* B0 =
            ((path == 0) ? g_osT : g_osT2) + (size_t)tb * CN + (size_t)n0 * CC;
        const float* gs = (path == 0) ? sg : tg;
        const float* bs = (path == 0) ? sb : tb_;
        tc_gemm_body<1>(A0, B0, 0, gs + 3 * CC, bs + 3 * CC,
                        g_ared + (size_t)tb * CC, g_a + (size_t)tb * CN,
                        o0, n0, path == 0);
        __syncthreads();
    }
}

// ---------------------------------------------------------------------------
// Phase 1 (merged): spatial kvM (blocks 0..479) + temporal gather (480..17759)
// ---------------------------------------------------------------------------
__global__ void __launch_bounds__(256) k_phase1() {
    const int bx = blockIdx.x;
    const int tid = threadIdx.x;
    if (bx < 480) {
        // spatial: M = k^T v per (t,b,h)
        __shared__ float ks[64][33];
        __shared__ float vs[64][33];
        const int tb = bx / HH;
        const int h = bx - tb * HH;
        const size_t base = (size_t)tb * CN + (size_t)h * 32 * NN;
        const __nv_bfloat16* kb = g_k + base;
        const __nv_bfloat16* vb = g_v + base;

        const int e = tid >> 3;
        const int dd0 = (tid & 7) << 2;
        float mc0 = 0.f, mc1 = 0.f, mc2 = 0.f, mc3 = 0.f;
        for (int m0 = 0; m0 < NN; m0 += 64) {
#pragma unroll
            for (int i = 0; i < 8; ++i) {
                int idx = tid + i * 256;
                int ee = idx >> 6, mm = idx & 63;
                ks[mm][ee] = __bfloat162float(kb[(size_t)ee * NN + m0 + mm]);
                vs[mm][ee] = __bfloat162float(vb[(size_t)ee * NN + m0 + mm]);
            }
            __syncthreads();
#pragma unroll 8
            for (int mm = 0; mm < 64; ++mm) {
                float kv = ks[mm][e];
                mc0 = fmaf(kv, vs[mm][dd0 + 0], mc0);
                mc1 = fmaf(kv, vs[mm][dd0 + 1], mc1);
                mc2 = fmaf(kv, vs[mm][dd0 + 2], mc2);
                mc3 = fmaf(kv, vs[mm][dd0 + 3], mc3);
            }
            __syncthreads();
        }
        float* Mp = g_M + (size_t)bx * 1024 + e * 32 + dd0;
        Mp[0] = mc0; Mp[1] = mc1; Mp[2] = mc2; Mp[3] = mc3;
    } else {
        // temporal gather: dst[((n*B+b)*H+h)*320 + t*32 + e]
        __shared__ __nv_bfloat16 tile[32][33];
        const int r0 = bx - 480;
        const int which = r0 / 5760;
        const int r = r0 - which * 5760;
        const int ntile = r % 12;
        const int tbh = r / 12;
        const int tb = tbh / 12;
        const int h = tbh - tb * 12;
        const int t = tb / BB;
        const int b = tb - t * BB;

        const __nv_bfloat16* srcbase = (which == 0) ? g_pq : (which == 1) ? g_pk : g_pv;
        __nv_bfloat16* dst = (which == 0) ? g_tq : (which == 1) ? g_tk : g_tv;
        const __nv_bfloat16* src = srcbase + (size_t)tb * CN + (size_t)h * 32 * NN + ntile * 32;

#pragma unroll
        for (int i = 0; i < 4; ++i) {
            int idx = tid + i * 256;
            int ee = idx >> 5, nn = idx & 31;
            tile[ee][nn] = src[(size_t)ee * NN + nn];
        }
        __syncthreads();
#pragma unroll
        for (int i = 0; i < 4; ++i) {
            int idx = tid + i * 256;
            int nn = idx >> 5, ee = idx & 31;
            int n = ntile * 32 + nn;
            dst[((size_t)(n * BB + b) * HH + h) * 320 + t * 32 + ee] = tile[ee][nn];
        }
    }
}

// ---------------------------------------------------------------------------
// Phase 2 (merged): spatial qM (blocks 0..1439) + temporal attn (1440..3743)
// ---------------------------------------------------------------------------
__global__ void __launch_bounds__(256) k_phase2() {
    const int bx = blockIdx.x;
    const int tid = threadIdx.x;
    if (bx < 1440) {
        // spatial: o = q M, spike >= 8, transposed bf16 into g_osT[tb][n][c]
        __shared__ float Ms[32][32];
        const int tbh = bx / 3;
        const int nt = bx - tbh * 3;
        const int tb = tbh / HH;
        const int h = tbh - tb * HH;

#pragma unroll
        for (int i = 0; i < 4; ++i) {
            int idx = tid + i * 256;
            Ms[idx >> 5][idx & 31] = g_M[(size_t)tbh * 1024 + idx];
        }
        __syncthreads();

        const int n = nt * 128 + (tid & 127);
        const int d0 = (tid >> 7) * 16;
        const __nv_bfloat16* qb = g_q + (size_t)tb * CN + (size_t)h * 32 * NN + n;

        float acc[16];
#pragma unroll
        for (int j = 0; j < 16; ++j) acc[j] = 0.f;
#pragma unroll
        for (int e = 0; e < 32; ++e) {
            float qv = __bfloat162float(qb[(size_t)e * NN]);
#pragma unroll
            for (int j = 0; j < 16; ++j) acc[j] = fmaf(qv, Ms[e][d0 + j], acc[j]);
        }
        __nv_bfloat16* op = g_osT + (size_t)tb * CN + (size_t)n * CC + h * 32 + d0;
#pragma unroll
        for (int j = 0; j < 16; j += 2) {
            __nv_bfloat162 p2;
            p2.x = __float2bfloat16((acc[j] >= 8.0f) ? 1.f : 0.f);
            p2.y = __float2bfloat16((acc[j + 1] >= 8.0f) ? 1.f : 0.f);
            *(__nv_bfloat162*)(op + j) = p2;
        }
    } else {
        // temporal attention per (n,b,h); spikes to g_osT2 via torch reshape
        __shared__ float qs[8][321];
        __shared__ float ks2[8][321];
        __shared__ float vs2[8][321];
        __shared__ float at[8][112];

        const int wid = tid >> 5;
        const int lane = tid & 31;
        const int nbh = (bx - 1440) * 8 + wid;
        const int h = nbh % HH;
        const int nb = nbh / HH;
        const int b = nb % BB;
        const int n = nb / BB;

        const __nv_bfloat16* qg = g_tq + (size_t)nbh * 320;
        const __nv_bfloat16* kg = g_tk + (size_t)nbh * 320;
        const __nv_bfloat16* vg = g_tv + (size_t)nbh * 320;

#pragma unroll
        for (int i = 0; i < TT; ++i) {
            qs[wid][lane * TT + i] = __bfloat162float(qg[i * 32 + lane]);
            ks2[wid][lane * TT + i] = __bfloat162float(kg[i * 32 + lane]);
            vs2[wid][i * 32 + lane] = __bfloat162float(vg[i * 32 + lane]);
        }
        __syncwarp();

        for (int ii = lane; ii < 100; ii += 32) {
            int t = ii / 10, s = ii - t * 10;
            float acc = 0.f;
#pragma unroll
            for (int ee = 0; ee < 32; ++ee)
                acc = fmaf(qs[wid][ee * TT + t], ks2[wid][ee * TT + s], acc);
            at[wid][ii] = acc;
        }
        __syncwarp();

#pragma unroll
        for (int t = 0; t < TT; ++t) {
            float acc = 0.f;
#pragma unroll
            for (int s = 0; s < TT; ++s)
                acc = fmaf(at[wid][t * 10 + s], vs2[wid][s * 32 + lane], acc);
            float sp = (acc >= 8.0f) ? 1.0f : 0.0f;
            int flat = h * 320 + t * 32 + lane;
            int tp = flat / 384;
            int cp = flat - tp * 384;
            g_osT2[(size_t)(tp * BB + b) * CN + (size_t)n * CC + cp] = __float2bfloat16(sp);
        }
    }
}

// ---------------------------------------------------------------------------
// reductions + outer product
// ---------------------------------------------------------------------------
__global__ void __launch_bounds__(256) k_reduce_b() {
    const int i = blockIdx.x * 256 + threadIdx.x;
    float s = 0.f;
#pragma unroll
    for (int t = 0; t < TT; ++t) s += __bfloat162float(g_a[(size_t)t * BCN + i]);
    g_bred[i] = s / (float)TT;
}

__global__ void __launch_bounds__(256) k_outer(float* __restrict__ out) { // 5760 blocks
    const int i = blockIdx.x * 256 + threadIdx.x;
    const int e = i * 4;
    const int n = e % NN;
    const int rest = e / NN;
    const int c = rest % CC;
    const int tb = rest / CC;
    const int b = tb % BB;
    const float a = g_ared[tb * CC + c] * (1.0f / 384.0f);
    const float* bp = &g_bred[((size_t)b * CC + c) * NN + n];
    float4 w;
    w.x = a * bp[0]; w.y = a * bp[1]; w.z = a * bp[2]; w.w = a * bp[3];
    *(float4*)(out + e) = w;
}

// ---------------------------------------------------------------------------
extern "C" void kernel_launch(void* const* d_in, const int* in_sizes, int n_in,
                              void* d_out, int out_size)
{
    const float* x   = (const float*)d_in[0];
    const float* y   = (const float*)d_in[1];
    const float* sW  = (const float*)d_in[2];
    const float* sg  = (const float*)d_in[3];
    const float* sb  = (const float*)d_in[4];
    const float* tW  = (const float*)d_in[5];
    const float* tg  = (const float*)d_in[6];
    const float* tbn = (const float*)d_in[7];
    float* out = (float*)d_out;

    cudaFuncSetAttribute(k_qkv_all, cudaFuncAttributeMaxDynamicSharedMemorySize, SMEM_QKV);
    cudaFuncSetAttribute(k_final_all, cudaFuncAttributeMaxDynamicSharedMemorySize, SMEM_FIN);

    // init + precompute splits
    k_init<<<60, 256>>>();
    k_split_w<<<4608, 256>>>(sW, tW);
    k_split_xy<<<11520, 256>>>(x, y);

    // all 6 qkv projections (both paths), work-queue persistent
    k_qkv_all<<<296, 256, SMEM_QKV>>>(sg, sb, tg, tbn);

    // phase 1: spatial k^T v  +  temporal gather (independent, one launch)
    k_phase1<<<480 + 3 * 5760, 256>>>();

    // phase 2: spatial qM  +  temporal attention (independent, one launch)
    k_phase2<<<1440 + (NN * BB * HH) / 8, 256>>>();

    // merged final convs (spatial fused row-mean + temporal), work-queue
    k_final_all<<<296, 256, SMEM_FIN>>>(sg, sb, tg, tbn);

    k_reduce_b<<<BCN / 256, 256>>>();

    // ---- combine ----
    k_outer<<<TBCN / 1024, 256>>>(out);
}